// round 2
// baseline (speedup 1.0000x reference)
#include <cuda_runtime.h>
#include <cuda_bf16.h>
#include <cstdint>
#include <cstddef>

// ---------------------------------------------------------------------------
// Problem constants
// ---------------------------------------------------------------------------
#define NBR   8
#define MROWS 16384              // B(32) * L(512)
#define BN_EPS 1e-5f

// ---------------------------------------------------------------------------
// Static device scratch (allocations are forbidden)
// ---------------------------------------------------------------------------
__device__ float g_bufA[NBR * MROWS * 512];    // 256 MB
__device__ float g_bufB[NBR * MROWS * 512];    // 256 MB
__device__ float g_h4  [NBR * MROWS * 64];     // 32 MB  (raw h4, pre-BN)
__device__ float g_t1  [NBR * MROWS * 64];     // 32 MB  (raw t1)
__device__ float g_t2  [NBR * MROWS * 128];    // 64 MB  (raw t2)
__device__ float g_t3  [NBR * MROWS * 128];    // 64 MB  (t3 logits, no BN)
// per-layer BN stats: 6 layer slices, each [NBR * 512] max channels
__device__ float g_psum [NBR * 512 * 128];     // partial col sums  [ch][mblock]
__device__ float g_psq  [NBR * 512 * 128];     // partial col sumsq
__device__ float g_scale[6 * NBR * 512];
__device__ float g_shift[6 * NBR * 512];

// ---------------------------------------------------------------------------
// helpers
// ---------------------------------------------------------------------------
__device__ __forceinline__ uint32_t smem_u32(const void* p) {
    uint32_t a;
    asm("{ .reg .u64 t; cvta.to.shared.u64 t, %1; cvt.u32.u64 %0, t; }"
        : "=r"(a) : "l"(p));
    return a;
}
__device__ __forceinline__ void st_cluster_f32(uint32_t saddr, uint32_t rank, float v) {
    uint32_t r;
    asm volatile("mapa.shared::cluster.u32 %0, %1, %2;" : "=r"(r) : "r"(saddr), "r"(rank));
    asm volatile("st.shared::cluster.f32 [%0], %1;" :: "r"(r), "f"(v) : "memory");
}
__device__ __forceinline__ void st_cluster_u32(uint32_t saddr, uint32_t rank, uint32_t v) {
    uint32_t r;
    asm volatile("mapa.shared::cluster.u32 %0, %1, %2;" : "=r"(r) : "r"(saddr), "r"(rank));
    asm volatile("st.shared::cluster.u32 [%0], %1;" :: "r"(r), "r"(v) : "memory");
}

// ---------------------------------------------------------------------------
// FPS: farthest point sampling. 4-CTA cluster per batch, 512 thr/CTA,
// 16 points per thread held in registers. Candidate exchange via DSMEM.
// Writes x_partial rows [1024, 2048) of the output.
// ---------------------------------------------------------------------------
#define FPS_CL 4
__global__ void __cluster_dims__(FPS_CL, 1, 1) __launch_bounds__(512, 1)
fps_kernel(const float* __restrict__ xpart, float* __restrict__ out)
{
    uint32_t rank;
    asm("mov.u32 %0, %%cluster_ctarank;" : "=r"(rank));
    int b = blockIdx.x / FPS_CL;
    const float* xp = xpart + (size_t)b * 32768 * 3;
    int tid = threadIdx.x;
    int pbase = (int)rank * 8192;

    float px[16], py[16], pz[16], dd[16];
#pragma unroll
    for (int i = 0; i < 16; i++) {
        int p = pbase + tid + 512 * i;
        px[i] = xp[p * 3 + 0];
        py[i] = xp[p * 3 + 1];
        pz[i] = xp[p * 3 + 2];
        dd[i] = 1e10f;
    }

    __shared__ float wv_[16]; __shared__ int wi_[16];
    __shared__ float wx_[16], wy_[16], wz_[16];
    __shared__ float cval[2][FPS_CL]; __shared__ int cidx[2][FPS_CL];
    __shared__ float cxx[2][FPS_CL], cyy[2][FPS_CL], czz[2][FPS_CL];

    float curx = xp[0], cury = xp[1], curz = xp[2];
    float* orow = out + ((size_t)b * 2048 + 1024) * 3;
    if (rank == 0 && tid == 0) { orow[0] = curx; orow[1] = cury; orow[2] = curz; }

    int lane = tid & 31, warp = tid >> 5;

    for (int t = 1; t < 1024; t++) {
        float bv = -1.f; int bi = 0x7fffffff;
        float bx = 0.f, by = 0.f, bz = 0.f;
#pragma unroll
        for (int i = 0; i < 16; i++) {
            float dx = __fsub_rn(px[i], curx);
            float dy = __fsub_rn(py[i], cury);
            float dz = __fsub_rn(pz[i], curz);
            float d  = __fadd_rn(__fadd_rn(__fmul_rn(dx, dx), __fmul_rn(dy, dy)),
                                 __fmul_rn(dz, dz));
            dd[i] = fminf(dd[i], d);
            int gi = pbase + tid + 512 * i;
            if (dd[i] > bv || (dd[i] == bv && gi < bi)) {
                bv = dd[i]; bi = gi; bx = px[i]; by = py[i]; bz = pz[i];
            }
        }
        // warp reduce (max value, tie -> lowest index)
#pragma unroll
        for (int s = 16; s > 0; s >>= 1) {
            float ov = __shfl_down_sync(0xffffffffu, bv, s);
            int   oi = __shfl_down_sync(0xffffffffu, bi, s);
            float ox = __shfl_down_sync(0xffffffffu, bx, s);
            float oy = __shfl_down_sync(0xffffffffu, by, s);
            float oz = __shfl_down_sync(0xffffffffu, bz, s);
            if (ov > bv || (ov == bv && oi < bi)) { bv = ov; bi = oi; bx = ox; by = oy; bz = oz; }
        }
        if (lane == 0) { wv_[warp] = bv; wi_[warp] = bi; wx_[warp] = bx; wy_[warp] = by; wz_[warp] = bz; }
        __syncthreads();
        int par = t & 1;
        if (warp == 0) {
            bv = (lane < 16) ? wv_[lane] : -1.f;
            bi = (lane < 16) ? wi_[lane] : 0x7fffffff;
            bx = (lane < 16) ? wx_[lane] : 0.f;
            by = (lane < 16) ? wy_[lane] : 0.f;
            bz = (lane < 16) ? wz_[lane] : 0.f;
#pragma unroll
            for (int s = 8; s > 0; s >>= 1) {
                float ov = __shfl_down_sync(0xffffffffu, bv, s);
                int   oi = __shfl_down_sync(0xffffffffu, bi, s);
                float ox = __shfl_down_sync(0xffffffffu, bx, s);
                float oy = __shfl_down_sync(0xffffffffu, by, s);
                float oz = __shfl_down_sync(0xffffffffu, bz, s);
                if (ov > bv || (ov == bv && oi < bi)) { bv = ov; bi = oi; bx = ox; by = oy; bz = oz; }
            }
            if (lane == 0) {
                for (uint32_t r = 0; r < FPS_CL; r++) {
                    st_cluster_f32(smem_u32(&cval[par][rank]), r, bv);
                    st_cluster_u32(smem_u32(&cidx[par][rank]), r, (uint32_t)bi);
                    st_cluster_f32(smem_u32(&cxx[par][rank]), r, bx);
                    st_cluster_f32(smem_u32(&cyy[par][rank]), r, by);
                    st_cluster_f32(smem_u32(&czz[par][rank]), r, bz);
                }
            }
        }
        asm volatile("barrier.cluster.arrive.aligned;" ::: "memory");
        asm volatile("barrier.cluster.wait.aligned;"   ::: "memory");

        float vv = cval[par][0]; int vi = cidx[par][0];
        float nx = cxx[par][0], ny = cyy[par][0], nz = czz[par][0];
#pragma unroll
        for (int r = 1; r < FPS_CL; r++) {
            float ov = cval[par][r]; int oi = cidx[par][r];
            if (ov > vv || (ov == vv && oi < vi)) {
                vv = ov; vi = oi; nx = cxx[par][r]; ny = cyy[par][r]; nz = czz[par][r];
            }
        }
        curx = nx; cury = ny; curz = nz;
        if (rank == 0 && tid == 0) {
            orow[t * 3 + 0] = nx; orow[t * 3 + 1] = ny; orow[t * 3 + 2] = nz;
        }
    }
}

// ---------------------------------------------------------------------------
// Generic fp32 tiled GEMM:  C[M,N] = f(A)[M,K] @ W[N,K]^T   per branch z.
// f = identity or relu(x*scale+shift) (fused BN+ReLU of previous layer).
// Optionally emits deterministic per-(channel, m-block) partial sums/sumsq.
// BM=128, BK=8, TM=8; BN/TN = 16 (256 threads).
// ---------------------------------------------------------------------------
template<int BN, int TN, bool HAS_T, bool HAS_S>
__global__ void __launch_bounds__(256)
gemm_bn(const float* __restrict__ Aall, const float* __restrict__ Wall,
        float* __restrict__ Call,
        const float* __restrict__ tsc, const float* __restrict__ tsh,
        float* __restrict__ psum, float* __restrict__ psq,
        int M, int N, int K, long aStride)
{
    constexpr int BM = 128, BK = 8, TM = 8;
    int z = blockIdx.z;
    const float* A = Aall + (size_t)z * (size_t)aStride;
    const float* W = Wall + (size_t)z * N * K;
    float* C = Call + (size_t)z * (size_t)M * N;
    const float* sc = HAS_T ? (tsc + z * K) : nullptr;
    const float* sh = HAS_T ? (tsh + z * K) : nullptr;

    __shared__ float As[BK][BM];
    __shared__ float Bs[BK][BN];
    __shared__ float red[16][BN];

    int t = threadIdx.x;
    int m0 = blockIdx.y * BM;
    int n0 = blockIdx.x * BN;
    int tcol = t & 15;
    int trow = t >> 4;

    float acc[TM][TN];
#pragma unroll
    for (int i = 0; i < TM; i++)
#pragma unroll
        for (int j = 0; j < TN; j++) acc[i][j] = 0.f;

    int ar = t >> 1, ac4 = (t & 1) * 4;
    const float* Aload = A + (size_t)(m0 + ar) * K + ac4;

    for (int k0 = 0; k0 < K; k0 += BK) {
        float4 av = *(const float4*)(Aload + k0);
        if (HAS_T) {
            int c = k0 + ac4;
            av.x = fmaxf(fmaf(av.x, sc[c + 0], sh[c + 0]), 0.f);
            av.y = fmaxf(fmaf(av.y, sc[c + 1], sh[c + 1]), 0.f);
            av.z = fmaxf(fmaf(av.z, sc[c + 2], sh[c + 2]), 0.f);
            av.w = fmaxf(fmaf(av.w, sc[c + 3], sh[c + 3]), 0.f);
        }
        As[ac4 + 0][ar] = av.x; As[ac4 + 1][ar] = av.y;
        As[ac4 + 2][ar] = av.z; As[ac4 + 3][ar] = av.w;

        for (int e = t; e < BN * 2; e += 256) {
            int wr = e >> 1, wc = (e & 1) * 4;
            float4 wvv = *(const float4*)(W + (size_t)(n0 + wr) * K + k0 + wc);
            Bs[wc + 0][wr] = wvv.x; Bs[wc + 1][wr] = wvv.y;
            Bs[wc + 2][wr] = wvv.z; Bs[wc + 3][wr] = wvv.w;
        }
        __syncthreads();
#pragma unroll
        for (int kk = 0; kk < BK; kk++) {
            float a[TM], bb[TN];
            {
                const float4* A4 = (const float4*)(&As[kk][trow * TM]);
                float4 t0 = A4[0], t1 = A4[1];
                a[0] = t0.x; a[1] = t0.y; a[2] = t0.z; a[3] = t0.w;
                a[4] = t1.x; a[5] = t1.y; a[6] = t1.z; a[7] = t1.w;
            }
            {
                const float4* B4 = (const float4*)(&Bs[kk][tcol * TN]);
                float4 u0 = B4[0];
                bb[0] = u0.x; bb[1] = u0.y; bb[2] = u0.z; bb[3] = u0.w;
                if constexpr (TN == 8) {
                    float4 u1 = B4[1];
                    bb[4] = u1.x; bb[5] = u1.y; bb[6] = u1.z; bb[7] = u1.w;
                }
            }
#pragma unroll
            for (int i = 0; i < TM; i++)
#pragma unroll
                for (int j = 0; j < TN; j++)
                    acc[i][j] = fmaf(a[i], bb[j], acc[i][j]);
        }
        __syncthreads();
    }

    // write raw C
#pragma unroll
    for (int i = 0; i < TM; i++) {
        float* crow = C + (size_t)(m0 + trow * TM + i) * N + n0 + tcol * TN;
#pragma unroll
        for (int j = 0; j < TN; j += 4) {
            float4 v = make_float4(acc[i][j], acc[i][j + 1], acc[i][j + 2], acc[i][j + 3]);
            *(float4*)(crow + j) = v;
        }
    }

    if (HAS_S) {
        float cs[TN], cq[TN];
#pragma unroll
        for (int j = 0; j < TN; j++) {
            cs[j] = 0.f; cq[j] = 0.f;
#pragma unroll
            for (int i = 0; i < TM; i++) {
                cs[j] += acc[i][j];
                cq[j] = fmaf(acc[i][j], acc[i][j], cq[j]);
            }
        }
        // sum pass
#pragma unroll
        for (int j = 0; j < TN; j++) red[trow][tcol * TN + j] = cs[j];
        __syncthreads();
        for (int s = 8; s > 0; s >>= 1) {
            if (trow < s)
#pragma unroll
                for (int j = 0; j < TN; j++)
                    red[trow][tcol * TN + j] += red[trow + s][tcol * TN + j];
            __syncthreads();
        }
        if (trow == 0)
#pragma unroll
            for (int j = 0; j < TN; j++)
                psum[(size_t)(z * N + n0 + tcol * TN + j) * 128 + blockIdx.y] =
                    red[0][tcol * TN + j];
        __syncthreads();
        // sumsq pass
#pragma unroll
        for (int j = 0; j < TN; j++) red[trow][tcol * TN + j] = cq[j];
        __syncthreads();
        for (int s = 8; s > 0; s >>= 1) {
            if (trow < s)
#pragma unroll
                for (int j = 0; j < TN; j++)
                    red[trow][tcol * TN + j] += red[trow + s][tcol * TN + j];
            __syncthreads();
        }
        if (trow == 0)
#pragma unroll
            for (int j = 0; j < TN; j++)
                psq[(size_t)(z * N + n0 + tcol * TN + j) * 128 + blockIdx.y] =
                    red[0][tcol * TN + j];
    }
}

// ---------------------------------------------------------------------------
// BN finalize: reduce 128 partials per (branch,channel), produce scale/shift
// ---------------------------------------------------------------------------
__global__ void bn_finalize(const float* __restrict__ psum, const float* __restrict__ psq,
                            const float* __restrict__ gam, const float* __restrict__ bet,
                            float* __restrict__ sc, float* __restrict__ sh, int total)
{
    int i = blockIdx.x * blockDim.x + threadIdx.x;
    if (i >= total) return;
    float s = 0.f, q = 0.f;
    const float* ps = psum + (size_t)i * 128;
    const float* pq = psq + (size_t)i * 128;
#pragma unroll 8
    for (int k = 0; k < 128; k++) { s += ps[k]; q += pq[k]; }
    float mean = s * (1.0f / 16384.0f);
    float var  = fmaf(-mean, mean, q * (1.0f / 16384.0f));
    float g = gam[i] * rsqrtf(var + BN_EPS);
    sc[i] = g;
    sh[i] = fmaf(-mean, g, bet[i]);
}

// ---------------------------------------------------------------------------
// Softmax over L + attention pooling + final 3-dim projection.
// One block per (batch, branch). base (512x64, BN-applied) staged in dynamic
// shared with stride 65 (conflict-free). Warp-per-channel softmax/pool.
// ---------------------------------------------------------------------------
__global__ void __launch_bounds__(256, 1)
softmax_pts_kernel(const float* __restrict__ t3, const float* __restrict__ h4raw,
                   const float* __restrict__ scaleL, const float* __restrict__ shiftL,
                   const float* __restrict__ aW4, const float* __restrict__ ab4,
                   float* __restrict__ out)
{
    int b = blockIdx.x;   // 0..31
    int n = blockIdx.y;   // 0..7
    extern __shared__ float base_sh[];      // [512][65]
    __shared__ float w4[3][64];
    __shared__ float b4[3];

    int tid = threadIdx.x;
    if (tid < 192) w4[tid / 64][tid % 64] = aW4[n * 192 + tid];
    if (tid < 3)   b4[tid] = ab4[n * 3 + tid];

    const float* sc = scaleL + n * 64;
    const float* sh = shiftL + n * 64;
    const float* h4b = h4raw + ((size_t)n * MROWS + b * 512) * 64;
    for (int i = tid; i < 512 * 64; i += 256) {
        int l = i >> 6, k = i & 63;
        float v = fmaxf(fmaf(h4b[i], sc[k], sh[k]), 0.f);
        base_sh[l * 65 + k] = v;
    }
    __syncthreads();

    int lane = tid & 31, warp = tid >> 5;
    const float* t3b = t3 + ((size_t)n * MROWS + b * 512) * 128;
    float* orow = out + ((size_t)b * 2048 + n * 128) * 3;

    for (int c = 0; c < 16; c++) {
        int m = warp + c * 8;
        float v[16];
        float mx = -1e30f;
#pragma unroll
        for (int i = 0; i < 16; i++) {
            v[i] = t3b[(size_t)(lane + 32 * i) * 128 + m];
            mx = fmaxf(mx, v[i]);
        }
#pragma unroll
        for (int s = 16; s > 0; s >>= 1) mx = fmaxf(mx, __shfl_xor_sync(0xffffffffu, mx, s));
        float sum = 0.f;
#pragma unroll
        for (int i = 0; i < 16; i++) { v[i] = expf(v[i] - mx); sum += v[i]; }
#pragma unroll
        for (int s = 16; s > 0; s >>= 1) sum += __shfl_xor_sync(0xffffffffu, sum, s);
        float inv = 1.0f / sum;
#pragma unroll
        for (int i = 0; i < 16; i++) v[i] *= inv;

        float o0 = 0.f, o1 = 0.f, o2 = 0.f;
        for (int k = 0; k < 64; k++) {
            float p = 0.f;
#pragma unroll
            for (int i = 0; i < 16; i++)
                p = fmaf(v[i], base_sh[(lane + 32 * i) * 65 + k], p);
#pragma unroll
            for (int s = 16; s > 0; s >>= 1) p += __shfl_xor_sync(0xffffffffu, p, s);
            o0 = fmaf(w4[0][k], p, o0);
            o1 = fmaf(w4[1][k], p, o1);
            o2 = fmaf(w4[2][k], p, o2);
        }
        if (lane == 0) {
            orow[m * 3 + 0] = o0 + b4[0];
            orow[m * 3 + 1] = o1 + b4[1];
            orow[m * 3 + 2] = o2 + b4[2];
        }
    }
}

// ---------------------------------------------------------------------------
// launch
// ---------------------------------------------------------------------------
extern "C" void kernel_launch(void* const* d_in, const int* in_sizes, int n_in,
                              void* d_out, int out_size)
{
    (void)in_sizes; (void)n_in; (void)out_size;
    const float* x     = (const float*)d_in[0];
    const float* xpart = (const float*)d_in[1];
    const float* mW1 = (const float*)d_in[2];
    const float* mg1 = (const float*)d_in[4];
    const float* mB1 = (const float*)d_in[5];
    const float* mW2 = (const float*)d_in[6];
    const float* mg2 = (const float*)d_in[8];
    const float* mB2 = (const float*)d_in[9];
    const float* mW3 = (const float*)d_in[10];
    const float* mg3 = (const float*)d_in[12];
    const float* mB3 = (const float*)d_in[13];
    const float* mW4 = (const float*)d_in[14];
    const float* mg4 = (const float*)d_in[16];
    const float* mB4 = (const float*)d_in[17];
    const float* aW1 = (const float*)d_in[18];
    const float* ag1 = (const float*)d_in[20];
    const float* aB1 = (const float*)d_in[21];
    const float* aW2 = (const float*)d_in[22];
    const float* ag2 = (const float*)d_in[24];
    const float* aB2 = (const float*)d_in[25];
    const float* aW3 = (const float*)d_in[26];
    const float* aW4 = (const float*)d_in[28];
    const float* ab4 = (const float*)d_in[29];
    float* out = (float*)d_out;

    float *bufA, *bufB, *h4, *t1, *t2, *t3, *psum, *psq, *sc, *sh;
    cudaGetSymbolAddress((void**)&bufA, g_bufA);
    cudaGetSymbolAddress((void**)&bufB, g_bufB);
    cudaGetSymbolAddress((void**)&h4,   g_h4);
    cudaGetSymbolAddress((void**)&t1,   g_t1);
    cudaGetSymbolAddress((void**)&t2,   g_t2);
    cudaGetSymbolAddress((void**)&t3,   g_t3);
    cudaGetSymbolAddress((void**)&psum, g_psum);
    cudaGetSymbolAddress((void**)&psq,  g_psq);
    cudaGetSymbolAddress((void**)&sc,   g_scale);
    cudaGetSymbolAddress((void**)&sh,   g_shift);

    static bool attr_done = false;
    if (!attr_done) {
        cudaFuncSetAttribute(softmax_pts_kernel,
                             cudaFuncAttributeMaxDynamicSharedMemorySize, 512 * 65 * 4);
        attr_done = true;
    }

    const int SL = NBR * 512;   // stats slice stride
    const long MS512 = (long)MROWS * 512;
    const long MS64  = (long)MROWS * 64;
    const long MS128 = (long)MROWS * 128;

    // FPS (independent of the GEMM chain)
    fps_kernel<<<32 * FPS_CL, 512>>>(xpart, out);

    // L1: x[16384,256] @ mW1^T -> bufA [16384,512]
    gemm_bn<128, 8, false, true><<<dim3(4, 128, NBR), 256>>>(
        x, mW1, bufA, nullptr, nullptr, psum, psq, MROWS, 512, 256, 0);
    bn_finalize<<<16, 256>>>(psum, psq, mg1, mB1, sc + 0 * SL, sh + 0 * SL, NBR * 512);

    // L2
    gemm_bn<128, 8, true, true><<<dim3(4, 128, NBR), 256>>>(
        bufA, mW2, bufB, sc + 0 * SL, sh + 0 * SL, psum, psq, MROWS, 512, 512, MS512);
    bn_finalize<<<16, 256>>>(psum, psq, mg2, mB2, sc + 1 * SL, sh + 1 * SL, NBR * 512);

    // L3
    gemm_bn<128, 8, true, true><<<dim3(4, 128, NBR), 256>>>(
        bufB, mW3, bufA, sc + 1 * SL, sh + 1 * SL, psum, psq, MROWS, 512, 512, MS512);
    bn_finalize<<<16, 256>>>(psum, psq, mg3, mB3, sc + 2 * SL, sh + 2 * SL, NBR * 512);

    // L4: -> h4 raw [16384,64]
    gemm_bn<64, 4, true, true><<<dim3(1, 128, NBR), 256>>>(
        bufA, mW4, h4, sc + 2 * SL, sh + 2 * SL, psum, psq, MROWS, 64, 512, MS512);
    bn_finalize<<<2, 256>>>(psum, psq, mg4, mB4, sc + 3 * SL, sh + 3 * SL, NBR * 64);

    // A1: base(h4) @ aW1^T -> t1 raw [16384,64]
    gemm_bn<64, 4, true, true><<<dim3(1, 128, NBR), 256>>>(
        h4, aW1, t1, sc + 3 * SL, sh + 3 * SL, psum, psq, MROWS, 64, 64, MS64);
    bn_finalize<<<2, 256>>>(psum, psq, ag1, aB1, sc + 4 * SL, sh + 4 * SL, NBR * 64);

    // A2: -> t2 raw [16384,128]
    gemm_bn<128, 8, true, true><<<dim3(1, 128, NBR), 256>>>(
        t1, aW2, t2, sc + 4 * SL, sh + 4 * SL, psum, psq, MROWS, 128, 64, MS64);
    bn_finalize<<<4, 256>>>(psum, psq, ag2, aB2, sc + 5 * SL, sh + 5 * SL, NBR * 128);

    // A3: -> t3 logits [16384,128] (no BN)
    gemm_bn<128, 8, true, false><<<dim3(1, 128, NBR), 256>>>(
        t2, aW3, t3, sc + 5 * SL, sh + 5 * SL, nullptr, nullptr, MROWS, 128, 128, MS128);

    // softmax + attention pool + projection -> x_1 rows [0,1024)
    softmax_pts_kernel<<<dim3(32, NBR), 256, 512 * 65 * 4>>>(
        t3, h4, sc + 3 * SL, sh + 3 * SL, aW4, ab4, out);
}

// round 3
// speedup vs baseline: 1.6385x; 1.6385x over previous
#include <cuda_runtime.h>
#include <cuda_bf16.h>
#include <cstdint>
#include <cstddef>

// ---------------------------------------------------------------------------
// Problem constants
// ---------------------------------------------------------------------------
#define NBR   8
#define MROWS 16384              // B(32) * L(512)
#define BN_EPS 1e-5f

// ---------------------------------------------------------------------------
// Static device scratch (allocations are forbidden)
// ---------------------------------------------------------------------------
__device__ float g_bufA[NBR * MROWS * 512];    // 256 MB
__device__ float g_bufB[NBR * MROWS * 512];    // 256 MB
__device__ float g_h4  [NBR * MROWS * 64];     // 32 MB  (raw h4, pre-BN)
__device__ float g_t1  [NBR * MROWS * 64];     // 32 MB  (raw t1)
__device__ float g_t2  [NBR * MROWS * 128];    // 64 MB  (raw t2)
__device__ float g_t3  [NBR * MROWS * 128];    // 64 MB  (t3 logits, no BN)
// per-layer BN stats: 6 layer slices, each [NBR * 512] max channels
__device__ float g_psum [NBR * 512 * 128];     // partial col sums  [ch][mblock]
__device__ float g_psq  [NBR * 512 * 128];     // partial col sumsq
__device__ float g_scale[6 * NBR * 512];
__device__ float g_shift[6 * NBR * 512];

// ---------------------------------------------------------------------------
// helpers
// ---------------------------------------------------------------------------
__device__ __forceinline__ uint32_t smem_u32(const void* p) {
    uint32_t a;
    asm("{ .reg .u64 t; cvta.to.shared.u64 t, %1; cvt.u32.u64 %0, t; }"
        : "=r"(a) : "l"(p));
    return a;
}
__device__ __forceinline__ void st_cluster_f32(uint32_t saddr, uint32_t rank, float v) {
    uint32_t r;
    asm volatile("mapa.shared::cluster.u32 %0, %1, %2;" : "=r"(r) : "r"(saddr), "r"(rank));
    asm volatile("st.shared::cluster.f32 [%0], %1;" :: "r"(r), "f"(v) : "memory");
}
__device__ __forceinline__ void st_cluster_u32(uint32_t saddr, uint32_t rank, uint32_t v) {
    uint32_t r;
    asm volatile("mapa.shared::cluster.u32 %0, %1, %2;" : "=r"(r) : "r"(saddr), "r"(rank));
    asm volatile("st.shared::cluster.u32 [%0], %1;" :: "r"(r), "r"(v) : "memory");
}

// ---------------------------------------------------------------------------
// FPS: farthest point sampling. 4-CTA cluster per batch, 512 thr/CTA,
// 16 points per thread held in registers. Candidate exchange via DSMEM.
// Writes x_partial rows [1024, 2048) of the output.
// ---------------------------------------------------------------------------
#define FPS_CL 4
__global__ void __cluster_dims__(FPS_CL, 1, 1) __launch_bounds__(512, 1)
fps_kernel(const float* __restrict__ xpart, float* __restrict__ out)
{
    uint32_t rank;
    asm("mov.u32 %0, %%cluster_ctarank;" : "=r"(rank));
    int b = blockIdx.x / FPS_CL;
    const float* xp = xpart + (size_t)b * 32768 * 3;
    int tid = threadIdx.x;
    int pbase = (int)rank * 8192;

    float px[16], py[16], pz[16], dd[16];
#pragma unroll
    for (int i = 0; i < 16; i++) {
        int p = pbase + tid + 512 * i;
        px[i] = xp[p * 3 + 0];
        py[i] = xp[p * 3 + 1];
        pz[i] = xp[p * 3 + 2];
        dd[i] = 1e10f;
    }

    __shared__ float wv_[16]; __shared__ int wi_[16];
    __shared__ float wx_[16], wy_[16], wz_[16];
    __shared__ float cval[2][FPS_CL]; __shared__ int cidx[2][FPS_CL];
    __shared__ float cxx[2][FPS_CL], cyy[2][FPS_CL], czz[2][FPS_CL];

    float curx = xp[0], cury = xp[1], curz = xp[2];
    float* orow = out + ((size_t)b * 2048 + 1024) * 3;
    if (rank == 0 && tid == 0) { orow[0] = curx; orow[1] = cury; orow[2] = curz; }

    int lane = tid & 31, warp = tid >> 5;

    for (int t = 1; t < 1024; t++) {
        float bv = -1.f; int bi = 0x7fffffff;
        float bx = 0.f, by = 0.f, bz = 0.f;
#pragma unroll
        for (int i = 0; i < 16; i++) {
            float dx = __fsub_rn(px[i], curx);
            float dy = __fsub_rn(py[i], cury);
            float dz = __fsub_rn(pz[i], curz);
            float d  = __fadd_rn(__fadd_rn(__fmul_rn(dx, dx), __fmul_rn(dy, dy)),
                                 __fmul_rn(dz, dz));
            dd[i] = fminf(dd[i], d);
            int gi = pbase + tid + 512 * i;
            if (dd[i] > bv || (dd[i] == bv && gi < bi)) {
                bv = dd[i]; bi = gi; bx = px[i]; by = py[i]; bz = pz[i];
            }
        }
        // warp reduce (max value, tie -> lowest index)
#pragma unroll
        for (int s = 16; s > 0; s >>= 1) {
            float ov = __shfl_down_sync(0xffffffffu, bv, s);
            int   oi = __shfl_down_sync(0xffffffffu, bi, s);
            float ox = __shfl_down_sync(0xffffffffu, bx, s);
            float oy = __shfl_down_sync(0xffffffffu, by, s);
            float oz = __shfl_down_sync(0xffffffffu, bz, s);
            if (ov > bv || (ov == bv && oi < bi)) { bv = ov; bi = oi; bx = ox; by = oy; bz = oz; }
        }
        if (lane == 0) { wv_[warp] = bv; wi_[warp] = bi; wx_[warp] = bx; wy_[warp] = by; wz_[warp] = bz; }
        __syncthreads();
        int par = t & 1;
        if (warp == 0) {
            bv = (lane < 16) ? wv_[lane] : -1.f;
            bi = (lane < 16) ? wi_[lane] : 0x7fffffff;
            bx = (lane < 16) ? wx_[lane] : 0.f;
            by = (lane < 16) ? wy_[lane] : 0.f;
            bz = (lane < 16) ? wz_[lane] : 0.f;
#pragma unroll
            for (int s = 8; s > 0; s >>= 1) {
                float ov = __shfl_down_sync(0xffffffffu, bv, s);
                int   oi = __shfl_down_sync(0xffffffffu, bi, s);
                float ox = __shfl_down_sync(0xffffffffu, bx, s);
                float oy = __shfl_down_sync(0xffffffffu, by, s);
                float oz = __shfl_down_sync(0xffffffffu, bz, s);
                if (ov > bv || (ov == bv && oi < bi)) { bv = ov; bi = oi; bx = ox; by = oy; bz = oz; }
            }
            if (lane == 0) {
                for (uint32_t r = 0; r < FPS_CL; r++) {
                    st_cluster_f32(smem_u32(&cval[par][rank]), r, bv);
                    st_cluster_u32(smem_u32(&cidx[par][rank]), r, (uint32_t)bi);
                    st_cluster_f32(smem_u32(&cxx[par][rank]), r, bx);
                    st_cluster_f32(smem_u32(&cyy[par][rank]), r, by);
                    st_cluster_f32(smem_u32(&czz[par][rank]), r, bz);
                }
            }
        }
        asm volatile("barrier.cluster.arrive.aligned;" ::: "memory");
        asm volatile("barrier.cluster.wait.aligned;"   ::: "memory");

        float vv = cval[par][0]; int vi = cidx[par][0];
        float nx = cxx[par][0], ny = cyy[par][0], nz = czz[par][0];
#pragma unroll
        for (int r = 1; r < FPS_CL; r++) {
            float ov = cval[par][r]; int oi = cidx[par][r];
            if (ov > vv || (ov == vv && oi < vi)) {
                vv = ov; vi = oi; nx = cxx[par][r]; ny = cyy[par][r]; nz = czz[par][r];
            }
        }
        curx = nx; cury = ny; curz = nz;
        if (rank == 0 && tid == 0) {
            orow[t * 3 + 0] = nx; orow[t * 3 + 1] = ny; orow[t * 3 + 2] = nz;
        }
    }
}

// ---------------------------------------------------------------------------
// Generic fp32 tiled GEMM:  C[M,N] = f(A)[M,K] @ W[N,K]^T   per branch z.
// f = identity or relu(x*scale+shift) (fused BN+ReLU of previous layer).
// Optionally emits deterministic per-(channel, m-block) partial sums/sumsq.
// BM=128, BK=8, TM=8; BN/TN = 16 (256 threads).
// ---------------------------------------------------------------------------
template<int BN, int TN, bool HAS_T, bool HAS_S>
__global__ void __launch_bounds__(256)
gemm_bn(const float* __restrict__ Aall, const float* __restrict__ Wall,
        float* __restrict__ Call,
        const float* __restrict__ tsc, const float* __restrict__ tsh,
        float* __restrict__ psum, float* __restrict__ psq,
        int M, int N, int K, long aStride)
{
    constexpr int BM = 128, BK = 8, TM = 8;
    int z = blockIdx.z;
    const float* A = Aall + (size_t)z * (size_t)aStride;
    const float* W = Wall + (size_t)z * N * K;
    float* C = Call + (size_t)z * (size_t)M * N;
    const float* sc = HAS_T ? (tsc + z * K) : nullptr;
    const float* sh = HAS_T ? (tsh + z * K) : nullptr;

    __shared__ float As[BK][BM];
    __shared__ float Bs[BK][BN];
    __shared__ float red[16][BN];

    int t = threadIdx.x;
    int m0 = blockIdx.y * BM;
    int n0 = blockIdx.x * BN;
    int tcol = t & 15;
    int trow = t >> 4;

    float acc[TM][TN];
#pragma unroll
    for (int i = 0; i < TM; i++)
#pragma unroll
        for (int j = 0; j < TN; j++) acc[i][j] = 0.f;

    int ar = t >> 1, ac4 = (t & 1) * 4;
    const float* Aload = A + (size_t)(m0 + ar) * K + ac4;

    for (int k0 = 0; k0 < K; k0 += BK) {
        float4 av = *(const float4*)(Aload + k0);
        if (HAS_T) {
            int c = k0 + ac4;
            av.x = fmaxf(fmaf(av.x, sc[c + 0], sh[c + 0]), 0.f);
            av.y = fmaxf(fmaf(av.y, sc[c + 1], sh[c + 1]), 0.f);
            av.z = fmaxf(fmaf(av.z, sc[c + 2], sh[c + 2]), 0.f);
            av.w = fmaxf(fmaf(av.w, sc[c + 3], sh[c + 3]), 0.f);
        }
        As[ac4 + 0][ar] = av.x; As[ac4 + 1][ar] = av.y;
        As[ac4 + 2][ar] = av.z; As[ac4 + 3][ar] = av.w;

        for (int e = t; e < BN * 2; e += 256) {
            int wr = e >> 1, wc = (e & 1) * 4;
            float4 wvv = *(const float4*)(W + (size_t)(n0 + wr) * K + k0 + wc);
            Bs[wc + 0][wr] = wvv.x; Bs[wc + 1][wr] = wvv.y;
            Bs[wc + 2][wr] = wvv.z; Bs[wc + 3][wr] = wvv.w;
        }
        __syncthreads();
#pragma unroll
        for (int kk = 0; kk < BK; kk++) {
            float a[TM], bb[TN];
            {
                const float4* A4 = (const float4*)(&As[kk][trow * TM]);
                float4 t0 = A4[0], t1 = A4[1];
                a[0] = t0.x; a[1] = t0.y; a[2] = t0.z; a[3] = t0.w;
                a[4] = t1.x; a[5] = t1.y; a[6] = t1.z; a[7] = t1.w;
            }
            {
                const float4* B4 = (const float4*)(&Bs[kk][tcol * TN]);
                float4 u0 = B4[0];
                bb[0] = u0.x; bb[1] = u0.y; bb[2] = u0.z; bb[3] = u0.w;
                if constexpr (TN == 8) {
                    float4 u1 = B4[1];
                    bb[4] = u1.x; bb[5] = u1.y; bb[6] = u1.z; bb[7] = u1.w;
                }
            }
#pragma unroll
            for (int i = 0; i < TM; i++)
#pragma unroll
                for (int j = 0; j < TN; j++)
                    acc[i][j] = fmaf(a[i], bb[j], acc[i][j]);
        }
        __syncthreads();
    }

    // write raw C
#pragma unroll
    for (int i = 0; i < TM; i++) {
        float* crow = C + (size_t)(m0 + trow * TM + i) * N + n0 + tcol * TN;
#pragma unroll
        for (int j = 0; j < TN; j += 4) {
            float4 v = make_float4(acc[i][j], acc[i][j + 1], acc[i][j + 2], acc[i][j + 3]);
            *(float4*)(crow + j) = v;
        }
    }

    if (HAS_S) {
        float cs[TN], cq[TN];
#pragma unroll
        for (int j = 0; j < TN; j++) {
            cs[j] = 0.f; cq[j] = 0.f;
#pragma unroll
            for (int i = 0; i < TM; i++) {
                cs[j] += acc[i][j];
                cq[j] = fmaf(acc[i][j], acc[i][j], cq[j]);
            }
        }
        // sum pass
#pragma unroll
        for (int j = 0; j < TN; j++) red[trow][tcol * TN + j] = cs[j];
        __syncthreads();
        for (int s = 8; s > 0; s >>= 1) {
            if (trow < s)
#pragma unroll
                for (int j = 0; j < TN; j++)
                    red[trow][tcol * TN + j] += red[trow + s][tcol * TN + j];
            __syncthreads();
        }
        if (trow == 0)
#pragma unroll
            for (int j = 0; j < TN; j++)
                psum[(size_t)(z * N + n0 + tcol * TN + j) * 128 + blockIdx.y] =
                    red[0][tcol * TN + j];
        __syncthreads();
        // sumsq pass
#pragma unroll
        for (int j = 0; j < TN; j++) red[trow][tcol * TN + j] = cq[j];
        __syncthreads();
        for (int s = 8; s > 0; s >>= 1) {
            if (trow < s)
#pragma unroll
                for (int j = 0; j < TN; j++)
                    red[trow][tcol * TN + j] += red[trow + s][tcol * TN + j];
            __syncthreads();
        }
        if (trow == 0)
#pragma unroll
            for (int j = 0; j < TN; j++)
                psq[(size_t)(z * N + n0 + tcol * TN + j) * 128 + blockIdx.y] =
                    red[0][tcol * TN + j];
    }
}

// ---------------------------------------------------------------------------
// BN finalize: reduce 128 partials per (branch,channel), produce scale/shift
// ---------------------------------------------------------------------------
__global__ void bn_finalize(const float* __restrict__ psum, const float* __restrict__ psq,
                            const float* __restrict__ gam, const float* __restrict__ bet,
                            float* __restrict__ sc, float* __restrict__ sh, int total)
{
    int i = blockIdx.x * blockDim.x + threadIdx.x;
    if (i >= total) return;
    float s = 0.f, q = 0.f;
    const float* ps = psum + (size_t)i * 128;
    const float* pq = psq + (size_t)i * 128;
#pragma unroll 8
    for (int k = 0; k < 128; k++) { s += ps[k]; q += pq[k]; }
    float mean = s * (1.0f / 16384.0f);
    float var  = fmaf(-mean, mean, q * (1.0f / 16384.0f));
    float g = gam[i] * rsqrtf(var + BN_EPS);
    sc[i] = g;
    sh[i] = fmaf(-mean, g, bet[i]);
}

// ---------------------------------------------------------------------------
// Softmax over L + attention pooling + final 3-dim projection.
// One block per (batch, branch). base (512x64, BN-applied) staged in dynamic
// shared with stride 65 (conflict-free). Warp-per-channel softmax/pool.
// ---------------------------------------------------------------------------
__global__ void __launch_bounds__(256, 1)
softmax_pts_kernel(const float* __restrict__ t3, const float* __restrict__ h4raw,
                   const float* __restrict__ scaleL, const float* __restrict__ shiftL,
                   const float* __restrict__ aW4, const float* __restrict__ ab4,
                   float* __restrict__ out)
{
    int b = blockIdx.x;   // 0..31
    int n = blockIdx.y;   // 0..7
    extern __shared__ float base_sh[];      // [512][65]
    __shared__ float w4[3][64];
    __shared__ float b4[3];

    int tid = threadIdx.x;
    if (tid < 192) w4[tid / 64][tid % 64] = aW4[n * 192 + tid];
    if (tid < 3)   b4[tid] = ab4[n * 3 + tid];

    const float* sc = scaleL + n * 64;
    const float* sh = shiftL + n * 64;
    const float* h4b = h4raw + ((size_t)n * MROWS + b * 512) * 64;
    for (int i = tid; i < 512 * 64; i += 256) {
        int l = i >> 6, k = i & 63;
        float v = fmaxf(fmaf(h4b[i], sc[k], sh[k]), 0.f);
        base_sh[l * 65 + k] = v;
    }
    __syncthreads();

    int lane = tid & 31, warp = tid >> 5;
    const float* t3b = t3 + ((size_t)n * MROWS + b * 512) * 128;
    float* orow = out + ((size_t)b * 2048 + n * 128) * 3;

    for (int c = 0; c < 16; c++) {
        int m = warp + c * 8;
        float v[16];
        float mx = -1e30f;
#pragma unroll
        for (int i = 0; i < 16; i++) {
            v[i] = t3b[(size_t)(lane + 32 * i) * 128 + m];
            mx = fmaxf(mx, v[i]);
        }
#pragma unroll
        for (int s = 16; s > 0; s >>= 1) mx = fmaxf(mx, __shfl_xor_sync(0xffffffffu, mx, s));
        float sum = 0.f;
#pragma unroll
        for (int i = 0; i < 16; i++) { v[i] = expf(v[i] - mx); sum += v[i]; }
#pragma unroll
        for (int s = 16; s > 0; s >>= 1) sum += __shfl_xor_sync(0xffffffffu, sum, s);
        float inv = 1.0f / sum;
#pragma unroll
        for (int i = 0; i < 16; i++) v[i] *= inv;

        float o0 = 0.f, o1 = 0.f, o2 = 0.f;
        for (int k = 0; k < 64; k++) {
            float p = 0.f;
#pragma unroll
            for (int i = 0; i < 16; i++)
                p = fmaf(v[i], base_sh[(lane + 32 * i) * 65 + k], p);
#pragma unroll
            for (int s = 16; s > 0; s >>= 1) p += __shfl_xor_sync(0xffffffffu, p, s);
            o0 = fmaf(w4[0][k], p, o0);
            o1 = fmaf(w4[1][k], p, o1);
            o2 = fmaf(w4[2][k], p, o2);
        }
        if (lane == 0) {
            orow[m * 3 + 0] = o0 + b4[0];
            orow[m * 3 + 1] = o1 + b4[1];
            orow[m * 3 + 2] = o2 + b4[2];
        }
    }
}

// ---------------------------------------------------------------------------
// launch
// ---------------------------------------------------------------------------
extern "C" void kernel_launch(void* const* d_in, const int* in_sizes, int n_in,
                              void* d_out, int out_size)
{
    (void)in_sizes; (void)n_in; (void)out_size;
    const float* x     = (const float*)d_in[0];
    const float* xpart = (const float*)d_in[1];
    const float* mW1 = (const float*)d_in[2];
    const float* mg1 = (const float*)d_in[4];
    const float* mB1 = (const float*)d_in[5];
    const float* mW2 = (const float*)d_in[6];
    const float* mg2 = (const float*)d_in[8];
    const float* mB2 = (const float*)d_in[9];
    const float* mW3 = (const float*)d_in[10];
    const float* mg3 = (const float*)d_in[12];
    const float* mB3 = (const float*)d_in[13];
    const float* mW4 = (const float*)d_in[14];
    const float* mg4 = (const float*)d_in[16];
    const float* mB4 = (const float*)d_in[17];
    const float* aW1 = (const float*)d_in[18];
    const float* ag1 = (const float*)d_in[20];
    const float* aB1 = (const float*)d_in[21];
    const float* aW2 = (const float*)d_in[22];
    const float* ag2 = (const float*)d_in[24];
    const float* aB2 = (const float*)d_in[25];
    const float* aW3 = (const float*)d_in[26];
    const float* aW4 = (const float*)d_in[28];
    const float* ab4 = (const float*)d_in[29];
    float* out = (float*)d_out;

    float *bufA, *bufB, *h4, *t1, *t2, *t3, *psum, *psq, *sc, *sh;
    cudaGetSymbolAddress((void**)&bufA, g_bufA);
    cudaGetSymbolAddress((void**)&bufB, g_bufB);
    cudaGetSymbolAddress((void**)&h4,   g_h4);
    cudaGetSymbolAddress((void**)&t1,   g_t1);
    cudaGetSymbolAddress((void**)&t2,   g_t2);
    cudaGetSymbolAddress((void**)&t3,   g_t3);
    cudaGetSymbolAddress((void**)&psum, g_psum);
    cudaGetSymbolAddress((void**)&psq,  g_psq);
    cudaGetSymbolAddress((void**)&sc,   g_scale);
    cudaGetSymbolAddress((void**)&sh,   g_shift);

    static bool attr_done = false;
    if (!attr_done) {
        cudaFuncSetAttribute(softmax_pts_kernel,
                             cudaFuncAttributeMaxDynamicSharedMemorySize, 512 * 65 * 4);
        attr_done = true;
    }

    const int SL = NBR * 512;   // stats slice stride
    const long MS512 = (long)MROWS * 512;
    const long MS64  = (long)MROWS * 64;
    const long MS128 = (long)MROWS * 128;

    // FPS (independent of the GEMM chain)
    fps_kernel<<<32 * FPS_CL, 512>>>(xpart, out);

    // L1: x[16384,256] @ mW1^T -> bufA [16384,512]
    gemm_bn<128, 8, false, true><<<dim3(4, 128, NBR), 256>>>(
        x, mW1, bufA, nullptr, nullptr, psum, psq, MROWS, 512, 256, 0);
    bn_finalize<<<16, 256>>>(psum, psq, mg1, mB1, sc + 0 * SL, sh + 0 * SL, NBR * 512);

    // L2
    gemm_bn<128, 8, true, true><<<dim3(4, 128, NBR), 256>>>(
        bufA, mW2, bufB, sc + 0 * SL, sh + 0 * SL, psum, psq, MROWS, 512, 512, MS512);
    bn_finalize<<<16, 256>>>(psum, psq, mg2, mB2, sc + 1 * SL, sh + 1 * SL, NBR * 512);

    // L3
    gemm_bn<128, 8, true, true><<<dim3(4, 128, NBR), 256>>>(
        bufB, mW3, bufA, sc + 1 * SL, sh + 1 * SL, psum, psq, MROWS, 512, 512, MS512);
    bn_finalize<<<16, 256>>>(psum, psq, mg3, mB3, sc + 2 * SL, sh + 2 * SL, NBR * 512);

    // L4: -> h4 raw [16384,64]
    gemm_bn<64, 4, true, true><<<dim3(1, 128, NBR), 256>>>(
        bufA, mW4, h4, sc + 2 * SL, sh + 2 * SL, psum, psq, MROWS, 64, 512, MS512);
    bn_finalize<<<2, 256>>>(psum, psq, mg4, mB4, sc + 3 * SL, sh + 3 * SL, NBR * 64);

    // A1: base(h4) @ aW1^T -> t1 raw [16384,64]
    gemm_bn<64, 4, true, true><<<dim3(1, 128, NBR), 256>>>(
        h4, aW1, t1, sc + 3 * SL, sh + 3 * SL, psum, psq, MROWS, 64, 64, MS64);
    bn_finalize<<<2, 256>>>(psum, psq, ag1, aB1, sc + 4 * SL, sh + 4 * SL, NBR * 64);

    // A2: -> t2 raw [16384,128]
    gemm_bn<128, 8, true, true><<<dim3(1, 128, NBR), 256>>>(
        t1, aW2, t2, sc + 4 * SL, sh + 4 * SL, psum, psq, MROWS, 128, 64, MS64);
    bn_finalize<<<4, 256>>>(psum, psq, ag2, aB2, sc + 5 * SL, sh + 5 * SL, NBR * 128);

    // A3: -> t3 logits [16384,128] (no BN)
    gemm_bn<128, 8, true, false><<<dim3(1, 128, NBR), 256>>>(
        t2, aW3, t3, sc + 5 * SL, sh + 5 * SL, nullptr, nullptr, MROWS, 128, 128, MS128);

    // softmax + attention pool + projection -> x_1 rows [0,1024)
    softmax_pts_kernel<<<dim3(32, NBR), 256, 512 * 65 * 4>>>(
        t3, h4, sc + 3 * SL, sh + 3 * SL, aW4, ab4, out);
}

// round 5
// speedup vs baseline: 2.2420x; 1.3683x over previous
#include <cuda_runtime.h>
#include <cuda_bf16.h>
#include <cstdint>
#include <cstddef>

#define NBR 8
#define MROWS 16384
#define BN_EPS 1e-5f

__device__ __align__(256) float g_bufA[(size_t)NBR * MROWS * 512];
__device__ __align__(256) float g_bufB[(size_t)NBR * MROWS * 512];
__device__ __align__(256) float g_h4 [(size_t)NBR * MROWS * 64];
__device__ __align__(256) float g_t1 [(size_t)NBR * MROWS * 64];
__device__ __align__(256) float g_t2 [(size_t)NBR * MROWS * 128];
__device__ __align__(256) float g_t3 [(size_t)NBR * MROWS * 128];
__device__ float g_psum [NBR * 512 * 128];
__device__ float g_psq  [NBR * 512 * 128];
__device__ float g_scale[6 * NBR * 512];
__device__ float g_shift[6 * NBR * 512];

__device__ __forceinline__ uint32_t smem_u32(const void* p) {
    uint32_t a;
    asm("{ .reg .u64 t; cvta.to.shared.u64 t, %1; cvt.u32.u64 %0, t; }" : "=r"(a) : "l"(p));
    return a;
}
__device__ __forceinline__ void stc_f32(uint32_t sa, uint32_t rank, float v) {
    uint32_t r;
    asm volatile("mapa.shared::cluster.u32 %0, %1, %2;" : "=r"(r) : "r"(sa), "r"(rank));
    asm volatile("st.shared::cluster.f32 [%0], %1;" :: "r"(r), "f"(v) : "memory");
}
__device__ __forceinline__ void stc_u32(uint32_t sa, uint32_t rank, uint32_t v) {
    uint32_t r;
    asm volatile("mapa.shared::cluster.u32 %0, %1, %2;" : "=r"(r) : "r"(sa), "r"(rank));
    asm volatile("st.shared::cluster.u32 [%0], %1;" :: "r"(r), "r"(v) : "memory");
}
#define LDSM4(R, ADDR) \
    asm volatile("ldmatrix.sync.aligned.m8n8.x4.shared.b16 {%0,%1,%2,%3}, [%4];" \
        : "=r"((R)[0]), "=r"((R)[1]), "=r"((R)[2]), "=r"((R)[3]) : "r"(ADDR))
#define MMA16816(D, A, B0, B1) \
    asm volatile("mma.sync.aligned.m16n8k16.row.col.f32.bf16.bf16.f32 " \
        "{%0,%1,%2,%3}, {%4,%5,%6,%7}, {%8,%9}, {%0,%1,%2,%3};" \
        : "+f"((D)[0]), "+f"((D)[1]), "+f"((D)[2]), "+f"((D)[3]) \
        : "r"((A)[0]), "r"((A)[1]), "r"((A)[2]), "r"((A)[3]), "r"(B0), "r"(B1))

// ------------------------------ FPS (R2-proven) -----------------------------
#define FPS_CL 4
__global__ void __cluster_dims__(FPS_CL,1,1) __launch_bounds__(512,1)
fps_kernel(const float* __restrict__ xpart, float* __restrict__ out)
{
    uint32_t rank; asm("mov.u32 %0, %%cluster_ctarank;" : "=r"(rank));
    int b = blockIdx.x / FPS_CL;
    const float* xp = xpart + (size_t)b * 32768 * 3;
    int tid = threadIdx.x, lane = tid & 31, warp = tid >> 5;
    int pbase = (int)rank * 8192;
    float px[16], py[16], pz[16], dd[16];
#pragma unroll
    for (int i = 0; i < 16; i++) {
        int p = pbase + tid + 512 * i;
        px[i] = xp[p*3]; py[i] = xp[p*3+1]; pz[i] = xp[p*3+2]; dd[i] = 1e10f;
    }
    __shared__ float wv_[16]; __shared__ int wi_[16];
    __shared__ float wx_[16], wy_[16], wz_[16];
    __shared__ float cval[2][FPS_CL]; __shared__ int cidx[2][FPS_CL];
    __shared__ float cxx[2][FPS_CL], cyy[2][FPS_CL], czz[2][FPS_CL];
    float curx = xp[0], cury = xp[1], curz = xp[2];
    float* orow = out + ((size_t)b * 2048 + 1024) * 3;
    if (rank == 0 && tid == 0) { orow[0]=curx; orow[1]=cury; orow[2]=curz; }

    for (int t = 1; t < 1024; t++) {
        float bv = -1.f; int bi = 0x7fffffff;
        float bx = 0.f, by = 0.f, bz = 0.f;
#pragma unroll
        for (int i = 0; i < 16; i++) {
            float dx = __fsub_rn(px[i], curx), dy = __fsub_rn(py[i], cury), dz = __fsub_rn(pz[i], curz);
            float d = __fadd_rn(__fadd_rn(__fmul_rn(dx,dx), __fmul_rn(dy,dy)), __fmul_rn(dz,dz));
            dd[i] = fminf(dd[i], d);
            int gi = pbase + tid + 512 * i;
            if (dd[i] > bv || (dd[i] == bv && gi < bi)) { bv=dd[i]; bi=gi; bx=px[i]; by=py[i]; bz=pz[i]; }
        }
#pragma unroll
        for (int s = 16; s > 0; s >>= 1) {
            float ov = __shfl_down_sync(0xffffffffu, bv, s);
            int   oi = __shfl_down_sync(0xffffffffu, bi, s);
            float ox = __shfl_down_sync(0xffffffffu, bx, s);
            float oy = __shfl_down_sync(0xffffffffu, by, s);
            float oz = __shfl_down_sync(0xffffffffu, bz, s);
            if (ov > bv || (ov == bv && oi < bi)) { bv=ov; bi=oi; bx=ox; by=oy; bz=oz; }
        }
        if (lane == 0) { wv_[warp]=bv; wi_[warp]=bi; wx_[warp]=bx; wy_[warp]=by; wz_[warp]=bz; }
        __syncthreads();
        int par = t & 1;
        if (warp == 0) {
            bv = (lane < 16) ? wv_[lane] : -1.f;
            bi = (lane < 16) ? wi_[lane] : 0x7fffffff;
            bx = (lane < 16) ? wx_[lane] : 0.f;
            by = (lane < 16) ? wy_[lane] : 0.f;
            bz = (lane < 16) ? wz_[lane] : 0.f;
#pragma unroll
            for (int s = 8; s > 0; s >>= 1) {
                float ov = __shfl_down_sync(0xffffffffu, bv, s);
                int   oi = __shfl_down_sync(0xffffffffu, bi, s);
                float ox = __shfl_down_sync(0xffffffffu, bx, s);
                float oy = __shfl_down_sync(0xffffffffu, by, s);
                float oz = __shfl_down_sync(0xffffffffu, bz, s);
                if (ov > bv || (ov == bv && oi < bi)) { bv=ov; bi=oi; bx=ox; by=oy; bz=oz; }
            }
            if (lane == 0) {
                for (uint32_t r = 0; r < FPS_CL; r++) {
                    stc_f32(smem_u32(&cval[par][rank]), r, bv);
                    stc_u32(smem_u32(&cidx[par][rank]), r, (uint32_t)bi);
                    stc_f32(smem_u32(&cxx[par][rank]), r, bx);
                    stc_f32(smem_u32(&cyy[par][rank]), r, by);
                    stc_f32(smem_u32(&czz[par][rank]), r, bz);
                }
            }
        }
        asm volatile("barrier.cluster.arrive.aligned;" ::: "memory");
        asm volatile("barrier.cluster.wait.aligned;" ::: "memory");
        float vv = cval[par][0]; int vi = cidx[par][0];
        float nx = cxx[par][0], ny = cyy[par][0], nz = czz[par][0];
#pragma unroll
        for (int r = 1; r < FPS_CL; r++) {
            float ov = cval[par][r]; int oi = cidx[par][r];
            if (ov > vv || (ov == vv && oi < vi)) { vv=ov; vi=oi; nx=cxx[par][r]; ny=cyy[par][r]; nz=czz[par][r]; }
        }
        curx = nx; cury = ny; curz = nz;
        if (rank == 0 && tid == 0) { orow[t*3]=nx; orow[t*3+1]=ny; orow[t*3+2]=nz; }
    }
}

// ------------------- bf16-split tensor-core GEMM (mma.sync) ----------------
// C[M,512] = f(A)[M,K] @ W[512,K]^T per branch. CTA 128x128, 8 warps 64x32.
__device__ __forceinline__ uint32_t packhi(float x, float y, float& lx, float& ly) {
    __nv_bfloat162 h; h.x = __float2bfloat16(x); h.y = __float2bfloat16(y);
    lx = x - __bfloat162float(h.x); ly = y - __bfloat162float(h.y);
    return *reinterpret_cast<uint32_t*>(&h);
}
__device__ __forceinline__ uint32_t packlo(float x, float y) {
    __nv_bfloat162 h; h.x = __float2bfloat16(x); h.y = __float2bfloat16(y);
    return *reinterpret_cast<uint32_t*>(&h);
}

template<bool HAS_T>
__global__ void __launch_bounds__(256, 1)
gemm_mma(const float* __restrict__ Aall, const float* __restrict__ Wall,
         float* __restrict__ Call, const float* __restrict__ tsc,
         const float* __restrict__ tsh, float* __restrict__ psum,
         float* __restrict__ psq, int K, long aStride)
{
    extern __shared__ __align__(16) uint32_t sm[];
    int bx = blockIdx.x, by = blockIdx.y, z = blockIdx.z;
    int tid = threadIdx.x, lane = tid & 31, w = tid >> 5;
    int wm = w & 1, wn = w >> 1;
    const float* A = Aall + (size_t)z * aStride;
    const float* W = Wall + (size_t)z * 512 * K;
    const float* sc = HAS_T ? tsc + z * K : nullptr;
    const float* sh = HAS_T ? tsh + z * K : nullptr;
    int m0 = by * 128, n0 = bx * 128;
    int KC = K >> 5;
    int lr = tid >> 1, lc0 = (tid & 1) * 16;
    const float* Ald = A + (size_t)(m0 + lr) * K + lc0;
    const float* Bld = W + (size_t)(n0 + lr) * K + lc0;

    float acc[4][4][4];
#pragma unroll
    for (int i = 0; i < 4; i++)
#pragma unroll
        for (int j = 0; j < 4; j++)
#pragma unroll
            for (int e = 0; e < 4; e++) acc[i][j][e] = 0.f;

    uint32_t sbase = smem_u32(sm);
    float av[16], bv[16];

    // prologue: load chunk 0
#pragma unroll
    for (int j = 0; j < 4; j++) {
        *(float4*)(av + 4*j) = *(const float4*)(Ald + 4*j);
        *(float4*)(bv + 4*j) = *(const float4*)(Bld + 4*j);
    }
    for (int kc = 0; kc < KC; kc++) {
        int s = kc & 1;
        // convert + store current chunk to stage s
        {
            if (HAS_T) {
#pragma unroll
                for (int j = 0; j < 16; j++) {
                    int c = kc * 32 + lc0 + j;
                    av[j] = fmaxf(fmaf(av[j], sc[c], sh[c]), 0.f);
                }
            }
            uint32_t* base = sm + s * 10240;
#pragma unroll
            for (int p = 0; p < 8; p++) {
                float lx, ly;
                uint32_t hi = packhi(av[2*p], av[2*p+1], lx, ly);
                base[lr*20 + (tid&1)*8 + p] = hi;
                base[2560 + lr*20 + (tid&1)*8 + p] = packlo(lx, ly);
                uint32_t bhi = packhi(bv[2*p], bv[2*p+1], lx, ly);
                base[5120 + lr*20 + (tid&1)*8 + p] = bhi;
                base[7680 + lr*20 + (tid&1)*8 + p] = packlo(lx, ly);
            }
        }
        __syncthreads();
        // prefetch next chunk (global loads overlap compute)
        if (kc + 1 < KC) {
#pragma unroll
            for (int j = 0; j < 4; j++) {
                *(float4*)(av + 4*j) = *(const float4*)(Ald + (kc+1)*32 + 4*j);
                *(float4*)(bv + 4*j) = *(const float4*)(Bld + (kc+1)*32 + 4*j);
            }
        }
        // compute stage s
        uint32_t abase = sbase + s * 40960 + (wm * 64) * 80;
        uint32_t bbase = sbase + s * 40960 + 5120 * 4 + (wn * 32) * 80;
        int arow = lane & 15, kh = (lane >> 4) * 8;
        int bn_ = ((lane >> 4) & 1) * 8 + (lane & 7), bk = ((lane >> 3) & 1) * 8;
#pragma unroll
        for (int ks = 0; ks < 2; ks++) {
            uint32_t ah[4][4], alr[4][4], bh[2][4], blr[2][4];
#pragma unroll
            for (int mt = 0; mt < 4; mt++) {
                uint32_t ad = abase + (mt*16 + arow) * 80 + (ks*16 + kh) * 2;
                LDSM4(ah[mt], ad);
                LDSM4(alr[mt], ad + 10240);
            }
#pragma unroll
            for (int g = 0; g < 2; g++) {
                uint32_t bd = bbase + (g*16 + bn_) * 80 + (ks*16 + bk) * 2;
                LDSM4(bh[g], bd);
                LDSM4(blr[g], bd + 10240);
            }
#pragma unroll
            for (int mt = 0; mt < 4; mt++)
#pragma unroll
                for (int nt = 0; nt < 4; nt++) {
                    int g = nt >> 1, p = (nt & 1) * 2;
                    MMA16816(acc[mt][nt], ah[mt],  bh[g][p],  bh[g][p+1]);
                    MMA16816(acc[mt][nt], ah[mt],  blr[g][p], blr[g][p+1]);
                    MMA16816(acc[mt][nt], alr[mt], bh[g][p],  bh[g][p+1]);
                }
        }
        __syncthreads();
    }

    // epilogue: accum -> smem (pitch 132), stats + coalesced store
    float* cs = (float*)sm;
#pragma unroll
    for (int mt = 0; mt < 4; mt++)
#pragma unroll
        for (int nt = 0; nt < 4; nt++) {
            int r = wm*64 + mt*16 + (lane >> 2);
            int c = wn*32 + nt*8 + (lane & 3) * 2;
            *(float2*)(cs + r*132 + c)       = make_float2(acc[mt][nt][0], acc[mt][nt][1]);
            *(float2*)(cs + (r+8)*132 + c)   = make_float2(acc[mt][nt][2], acc[mt][nt][3]);
        }
    __syncthreads();
    if (tid < 128) {
        float s = 0.f, q = 0.f;
#pragma unroll 8
        for (int r = 0; r < 128; r++) { float v = cs[r*132 + tid]; s += v; q = fmaf(v, v, q); }
        size_t ch = (size_t)z * 512 + n0 + tid;
        psum[ch * 128 + by] = s; psq[ch * 128 + by] = q;
    }
    float* C = Call + (size_t)z * MROWS * 512;
#pragma unroll
    for (int i = 0; i < 16; i++) {
        int lin = tid + 256 * i;
        int r = lin >> 5, c4 = (lin & 31) * 4;
        float4 v = *(float4*)(cs + r*132 + c4);
        *(float4*)(C + (size_t)(m0 + r) * 512 + n0 + c4) = v;
    }
}

// --------------------------- SIMT small GEMM (R2) ---------------------------
template<int BN, int TN, bool HAS_T, bool HAS_S>
__global__ void __launch_bounds__(256)
gemm_bn(const float* __restrict__ Aall, const float* __restrict__ Wall, float* __restrict__ Call,
        const float* __restrict__ tsc, const float* __restrict__ tsh,
        float* __restrict__ psum, float* __restrict__ psq, int M, int N, int K, long aStride)
{
    constexpr int BM = 128, BK = 8, TM = 8;
    int z = blockIdx.z;
    const float* A = Aall + (size_t)z * (size_t)aStride;
    const float* W = Wall + (size_t)z * N * K;
    float* C = Call + (size_t)z * (size_t)M * N;
    const float* sc = HAS_T ? (tsc + z * K) : nullptr;
    const float* sh = HAS_T ? (tsh + z * K) : nullptr;
    __shared__ float As[BK][BM], Bs[BK][BN], red[16][BN];
    int t = threadIdx.x, m0 = blockIdx.y * BM, n0 = blockIdx.x * BN;
    int tcol = t & 15, trow = t >> 4;
    float acc[TM][TN];
#pragma unroll
    for (int i = 0; i < TM; i++)
#pragma unroll
        for (int j = 0; j < TN; j++) acc[i][j] = 0.f;
    int ar = t >> 1, ac4 = (t & 1) * 4;
    const float* Aload = A + (size_t)(m0 + ar) * K + ac4;
    for (int k0 = 0; k0 < K; k0 += BK) {
        float4 avv = *(const float4*)(Aload + k0);
        if (HAS_T) {
            int c = k0 + ac4;
            avv.x = fmaxf(fmaf(avv.x, sc[c],   sh[c]),   0.f);
            avv.y = fmaxf(fmaf(avv.y, sc[c+1], sh[c+1]), 0.f);
            avv.z = fmaxf(fmaf(avv.z, sc[c+2], sh[c+2]), 0.f);
            avv.w = fmaxf(fmaf(avv.w, sc[c+3], sh[c+3]), 0.f);
        }
        As[ac4][ar] = avv.x; As[ac4+1][ar] = avv.y; As[ac4+2][ar] = avv.z; As[ac4+3][ar] = avv.w;
        for (int e = t; e < BN * 2; e += 256) {
            int wr = e >> 1, wc = (e & 1) * 4;
            float4 wv = *(const float4*)(W + (size_t)(n0 + wr) * K + k0 + wc);
            Bs[wc][wr] = wv.x; Bs[wc+1][wr] = wv.y; Bs[wc+2][wr] = wv.z; Bs[wc+3][wr] = wv.w;
        }
        __syncthreads();
#pragma unroll
        for (int kk = 0; kk < BK; kk++) {
            float a[TM], bb[TN];
            const float4* A4 = (const float4*)(&As[kk][trow * TM]);
            float4 t0 = A4[0], t1 = A4[1];
            a[0]=t0.x; a[1]=t0.y; a[2]=t0.z; a[3]=t0.w; a[4]=t1.x; a[5]=t1.y; a[6]=t1.z; a[7]=t1.w;
            const float4* B4 = (const float4*)(&Bs[kk][tcol * TN]);
            float4 u0 = B4[0];
            bb[0]=u0.x; bb[1]=u0.y; bb[2]=u0.z; bb[3]=u0.w;
            if constexpr (TN == 8) { float4 u1 = B4[1]; bb[4]=u1.x; bb[5]=u1.y; bb[6]=u1.z; bb[7]=u1.w; }
#pragma unroll
            for (int i = 0; i < TM; i++)
#pragma unroll
                for (int j = 0; j < TN; j++) acc[i][j] = fmaf(a[i], bb[j], acc[i][j]);
        }
        __syncthreads();
    }
#pragma unroll
    for (int i = 0; i < TM; i++) {
        float* crow = C + (size_t)(m0 + trow * TM + i) * N + n0 + tcol * TN;
#pragma unroll
        for (int j = 0; j < TN; j += 4)
            *(float4*)(crow + j) = make_float4(acc[i][j], acc[i][j+1], acc[i][j+2], acc[i][j+3]);
    }
    if (HAS_S) {
        float cs2[TN], cq[TN];
#pragma unroll
        for (int j = 0; j < TN; j++) {
            cs2[j] = 0.f; cq[j] = 0.f;
#pragma unroll
            for (int i = 0; i < TM; i++) { cs2[j] += acc[i][j]; cq[j] = fmaf(acc[i][j], acc[i][j], cq[j]); }
        }
#pragma unroll
        for (int j = 0; j < TN; j++) red[trow][tcol * TN + j] = cs2[j];
        __syncthreads();
        for (int s = 8; s > 0; s >>= 1) {
            if (trow < s)
#pragma unroll
                for (int j = 0; j < TN; j++) red[trow][tcol*TN+j] += red[trow+s][tcol*TN+j];
            __syncthreads();
        }
        if (trow == 0)
#pragma unroll
            for (int j = 0; j < TN; j++)
                psum[(size_t)(z * N + n0 + tcol * TN + j) * 128 + blockIdx.y] = red[0][tcol*TN+j];
        __syncthreads();
#pragma unroll
        for (int j = 0; j < TN; j++) red[trow][tcol * TN + j] = cq[j];
        __syncthreads();
        for (int s = 8; s > 0; s >>= 1) {
            if (trow < s)
#pragma unroll
                for (int j = 0; j < TN; j++) red[trow][tcol*TN+j] += red[trow+s][tcol*TN+j];
            __syncthreads();
        }
        if (trow == 0)
#pragma unroll
            for (int j = 0; j < TN; j++)
                psq[(size_t)(z * N + n0 + tcol * TN + j) * 128 + blockIdx.y] = red[0][tcol*TN+j];
    }
}

__global__ void bn_finalize(const float* __restrict__ psum, const float* __restrict__ psq,
                            const float* __restrict__ gam, const float* __restrict__ bet,
                            float* __restrict__ sc, float* __restrict__ sh, int total)
{
    int i = blockIdx.x * blockDim.x + threadIdx.x;
    if (i >= total) return;
    float s = 0.f, q = 0.f;
    const float* ps = psum + (size_t)i * 128;
    const float* pq = psq + (size_t)i * 128;
#pragma unroll 8
    for (int k = 0; k < 128; k++) { s += ps[k]; q += pq[k]; }
    float mean = s * (1.f / 16384.f);
    float var = fmaf(-mean, mean, q * (1.f / 16384.f));
    float g = gam[i] * rsqrtf(var + BN_EPS);
    sc[i] = g; sh[i] = fmaf(-mean, g, bet[i]);
}

// ----------------------------- softmax/pool (R2) ----------------------------
__global__ void __launch_bounds__(256, 1)
softmax_pts_kernel(const float* __restrict__ t3, const float* __restrict__ h4raw,
                   const float* __restrict__ scaleL, const float* __restrict__ shiftL,
                   const float* __restrict__ aW4, const float* __restrict__ ab4,
                   float* __restrict__ out)
{
    int b = blockIdx.x, n = blockIdx.y;
    extern __shared__ float base_sh[];
    __shared__ float w4[3][64], b4[3];
    int tid = threadIdx.x;
    if (tid < 192) w4[tid / 64][tid % 64] = aW4[n * 192 + tid];
    if (tid < 3) b4[tid] = ab4[n * 3 + tid];
    const float* sc = scaleL + n * 64;
    const float* sh = shiftL + n * 64;
    const float* h4b = h4raw + ((size_t)n * MROWS + b * 512) * 64;
    for (int i = tid; i < 512 * 64; i += 256) {
        int l = i >> 6, k = i & 63;
        base_sh[l * 65 + k] = fmaxf(fmaf(h4b[i], sc[k], sh[k]), 0.f);
    }
    __syncthreads();
    int lane = tid & 31, warp = tid >> 5;
    const float* t3b = t3 + ((size_t)n * MROWS + b * 512) * 128;
    float* orow = out + ((size_t)b * 2048 + n * 128) * 3;
    for (int c = 0; c < 16; c++) {
        int m = warp + c * 8;
        float v[16], mx = -1e30f;
#pragma unroll
        for (int i = 0; i < 16; i++) { v[i] = t3b[(size_t)(lane + 32*i) * 128 + m]; mx = fmaxf(mx, v[i]); }
#pragma unroll
        for (int s = 16; s > 0; s >>= 1) mx = fmaxf(mx, __shfl_xor_sync(0xffffffffu, mx, s));
        float sum = 0.f;
#pragma unroll
        for (int i = 0; i < 16; i++) { v[i] = expf(v[i] - mx); sum += v[i]; }
#pragma unroll
        for (int s = 16; s > 0; s >>= 1) sum += __shfl_xor_sync(0xffffffffu, sum, s);
        float inv = 1.f / sum;
#pragma unroll
        for (int i = 0; i < 16; i++) v[i] *= inv;
        float o0 = 0.f, o1 = 0.f, o2 = 0.f;
        for (int k = 0; k < 64; k++) {
            float p = 0.f;
#pragma unroll
            for (int i = 0; i < 16; i++) p = fmaf(v[i], base_sh[(lane + 32*i) * 65 + k], p);
#pragma unroll
            for (int s = 16; s > 0; s >>= 1) p += __shfl_xor_sync(0xffffffffu, p, s);
            o0 = fmaf(w4[0][k], p, o0); o1 = fmaf(w4[1][k], p, o1); o2 = fmaf(w4[2][k], p, o2);
        }
        if (lane == 0) { orow[m*3] = o0 + b4[0]; orow[m*3+1] = o1 + b4[1]; orow[m*3+2] = o2 + b4[2]; }
    }
}

// ------------------------------- launch ------------------------------------
extern "C" void kernel_launch(void* const* d_in, const int* in_sizes, int n_in,
                              void* d_out, int out_size)
{
    (void)in_sizes; (void)n_in; (void)out_size;
    const float* x     = (const float*)d_in[0];
    const float* xpart = (const float*)d_in[1];
    const float* mW1 = (const float*)d_in[2];
    const float* mg1 = (const float*)d_in[4];
    const float* mB1 = (const float*)d_in[5];
    const float* mW2 = (const float*)d_in[6];
    const float* mg2 = (const float*)d_in[8];
    const float* mB2 = (const float*)d_in[9];
    const float* mW3 = (const float*)d_in[10];
    const float* mg3 = (const float*)d_in[12];
    const float* mB3 = (const float*)d_in[13];
    const float* mW4 = (const float*)d_in[14];
    const float* mg4 = (const float*)d_in[16];
    const float* mB4 = (const float*)d_in[17];
    const float* aW1 = (const float*)d_in[18];
    const float* ag1 = (const float*)d_in[20];
    const float* aB1 = (const float*)d_in[21];
    const float* aW2 = (const float*)d_in[22];
    const float* ag2 = (const float*)d_in[24];
    const float* aB2 = (const float*)d_in[25];
    const float* aW3 = (const float*)d_in[26];
    const float* aW4 = (const float*)d_in[28];
    const float* ab4 = (const float*)d_in[29];
    float* out = (float*)d_out;

    float *bufA, *bufB, *h4, *t1, *t2, *t3, *psum, *psq, *sc, *sh;
    cudaGetSymbolAddress((void**)&bufA, g_bufA);
    cudaGetSymbolAddress((void**)&bufB, g_bufB);
    cudaGetSymbolAddress((void**)&h4, g_h4);
    cudaGetSymbolAddress((void**)&t1, g_t1);
    cudaGetSymbolAddress((void**)&t2, g_t2);
    cudaGetSymbolAddress((void**)&t3, g_t3);
    cudaGetSymbolAddress((void**)&psum, g_psum);
    cudaGetSymbolAddress((void**)&psq, g_psq);
    cudaGetSymbolAddress((void**)&sc, g_scale);
    cudaGetSymbolAddress((void**)&sh, g_shift);

    static bool attr_done = false;
    if (!attr_done) {
        cudaFuncSetAttribute(softmax_pts_kernel, cudaFuncAttributeMaxDynamicSharedMemorySize, 512 * 65 * 4);
        cudaFuncSetAttribute(gemm_mma<false>, cudaFuncAttributeMaxDynamicSharedMemorySize, 81920);
        cudaFuncSetAttribute(gemm_mma<true>,  cudaFuncAttributeMaxDynamicSharedMemorySize, 81920);
        attr_done = true;
    }

    const int SL = NBR * 512;
    const long MS512 = (long)MROWS * 512;
    const long MS64  = (long)MROWS * 64;
    const long MS128 = (long)MROWS * 128;

    fps_kernel<<<32 * FPS_CL, 512>>>(xpart, out);

    // L1: x @ mW1^T -> bufA  (tensor cores, bf16 split)
    gemm_mma<false><<<dim3(4, 128, NBR), 256, 81920>>>(
        x, mW1, bufA, nullptr, nullptr, psum, psq, 256, 0);
    bn_finalize<<<16, 256>>>(psum, psq, mg1, mB1, sc, sh, NBR * 512);

    // L2: bufA -> bufB
    gemm_mma<true><<<dim3(4, 128, NBR), 256, 81920>>>(
        bufA, mW2, bufB, sc, sh, psum, psq, 512, MS512);
    bn_finalize<<<16, 256>>>(psum, psq, mg2, mB2, sc + SL, sh + SL, NBR * 512);

    // L3: bufB -> bufA
    gemm_mma<true><<<dim3(4, 128, NBR), 256, 81920>>>(
        bufB, mW3, bufA, sc + SL, sh + SL, psum, psq, 512, MS512);
    bn_finalize<<<16, 256>>>(psum, psq, mg3, mB3, sc + 2 * SL, sh + 2 * SL, NBR * 512);

    gemm_bn<64, 4, true, true><<<dim3(1, 128, NBR), 256>>>(
        bufA, mW4, h4, sc + 2 * SL, sh + 2 * SL, psum, psq, MROWS, 64, 512, MS512);
    bn_finalize<<<2, 256>>>(psum, psq, mg4, mB4, sc + 3 * SL, sh + 3 * SL, NBR * 64);

    gemm_bn<64, 4, true, true><<<dim3(1, 128, NBR), 256>>>(
        h4, aW1, t1, sc + 3 * SL, sh + 3 * SL, psum, psq, MROWS, 64, 64, MS64);
    bn_finalize<<<2, 256>>>(psum, psq, ag1, aB1, sc + 4 * SL, sh + 4 * SL, NBR * 64);

    gemm_bn<128, 8, true, true><<<dim3(1, 128, NBR), 256>>>(
        t1, aW2, t2, sc + 4 * SL, sh + 4 * SL, psum, psq, MROWS, 128, 64, MS64);
    bn_finalize<<<4, 256>>>(psum, psq, ag2, aB2, sc + 5 * SL, sh + 5 * SL, NBR * 128);

    gemm_bn<128, 8, true, false><<<dim3(1, 128, NBR), 256>>>(
        t2, aW3, t3, sc + 5 * SL, sh + 5 * SL, nullptr, nullptr, MROWS, 128, 128, MS128);

    softmax_pts_kernel<<<dim3(32, NBR), 256, 512 * 65 * 4>>>(
        t3, h4, sc + 3 * SL, sh + 3 * SL, aW4, ab4, out);
}

// round 6
// speedup vs baseline: 2.4087x; 1.0744x over previous
#include <cuda_runtime.h>
#include <cuda_bf16.h>
#include <cstdint>
#include <cstddef>

#define NBR 8
#define MROWS 16384
#define BN_EPS 1e-5f

__device__ __align__(256) float g_bufA[(size_t)NBR * MROWS * 512];
__device__ __align__(256) float g_bufB[(size_t)NBR * MROWS * 512];
__device__ __align__(256) float g_h4 [(size_t)NBR * MROWS * 64];
__device__ __align__(256) float g_t1 [(size_t)NBR * MROWS * 64];
__device__ __align__(256) float g_t2 [(size_t)NBR * MROWS * 128];
__device__ __align__(256) float g_t3 [(size_t)NBR * MROWS * 128];
__device__ float g_psum [NBR * 512 * 128];
__device__ float g_psq  [NBR * 512 * 128];
__device__ float g_scale[6 * NBR * 512];
__device__ float g_shift[6 * NBR * 512];
__device__ __align__(16) __nv_bfloat16 g_Ah[(size_t)NBR * MROWS * 512];
__device__ __align__(16) __nv_bfloat16 g_Al[(size_t)NBR * MROWS * 512];
__device__ __align__(16) __nv_bfloat16 g_Xh[(size_t)MROWS * 256];
__device__ __align__(16) __nv_bfloat16 g_Xl[(size_t)MROWS * 256];
__device__ __align__(16) __nv_bfloat16 g_W1h[NBR * 512 * 256];
__device__ __align__(16) __nv_bfloat16 g_W1l[NBR * 512 * 256];
__device__ __align__(16) __nv_bfloat16 g_W2h[NBR * 512 * 512];
__device__ __align__(16) __nv_bfloat16 g_W2l[NBR * 512 * 512];
__device__ __align__(16) __nv_bfloat16 g_W3h[NBR * 512 * 512];
__device__ __align__(16) __nv_bfloat16 g_W3l[NBR * 512 * 512];

__device__ __forceinline__ uint32_t smem_u32(const void* p) {
    uint32_t a;
    asm("{ .reg .u64 t; cvta.to.shared.u64 t, %1; cvt.u32.u64 %0, t; }" : "=r"(a) : "l"(p));
    return a;
}
__device__ __forceinline__ void stc_f32(uint32_t sa, uint32_t rank, float v) {
    uint32_t r;
    asm volatile("mapa.shared::cluster.u32 %0, %1, %2;" : "=r"(r) : "r"(sa), "r"(rank));
    asm volatile("st.shared::cluster.f32 [%0], %1;" :: "r"(r), "f"(v) : "memory");
}
__device__ __forceinline__ void stc_u32(uint32_t sa, uint32_t rank, uint32_t v) {
    uint32_t r;
    asm volatile("mapa.shared::cluster.u32 %0, %1, %2;" : "=r"(r) : "r"(sa), "r"(rank));
    asm volatile("st.shared::cluster.u32 [%0], %1;" :: "r"(r), "r"(v) : "memory");
}
__device__ __forceinline__ void cpa16(uint32_t d, const void* g) {
    asm volatile("cp.async.cg.shared.global [%0], [%1], 16;" :: "r"(d), "l"(g));
}
#define CP_COMMIT() asm volatile("cp.async.commit_group;")
#define CP_WAIT(N)  asm volatile("cp.async.wait_group %0;" :: "n"(N))
#define LDSM4(R, ADDR) \
    asm volatile("ldmatrix.sync.aligned.m8n8.x4.shared.b16 {%0,%1,%2,%3}, [%4];" \
        : "=r"((R)[0]), "=r"((R)[1]), "=r"((R)[2]), "=r"((R)[3]) : "r"(ADDR))
#define MMA16816(D, A, B0, B1) \
    asm volatile("mma.sync.aligned.m16n8k16.row.col.f32.bf16.bf16.f32 " \
        "{%0,%1,%2,%3}, {%4,%5,%6,%7}, {%8,%9}, {%0,%1,%2,%3};" \
        : "+f"((D)[0]), "+f"((D)[1]), "+f"((D)[2]), "+f"((D)[3]) \
        : "r"((A)[0]), "r"((A)[1]), "r"((A)[2]), "r"((A)[3]), "r"(B0), "r"(B1))

// ------------------------------ FPS (proven) --------------------------------
#define FPS_CL 4
__global__ void __cluster_dims__(FPS_CL,1,1) __launch_bounds__(512,1)
fps_kernel(const float* __restrict__ xpart, float* __restrict__ out)
{
    uint32_t rank; asm("mov.u32 %0, %%cluster_ctarank;" : "=r"(rank));
    int b = blockIdx.x / FPS_CL;
    const float* xp = xpart + (size_t)b * 32768 * 3;
    int tid = threadIdx.x, lane = tid & 31, warp = tid >> 5;
    int pbase = (int)rank * 8192;
    float px[16], py[16], pz[16], dd[16];
#pragma unroll
    for (int i = 0; i < 16; i++) {
        int p = pbase + tid + 512 * i;
        px[i] = xp[p*3]; py[i] = xp[p*3+1]; pz[i] = xp[p*3+2]; dd[i] = 1e10f;
    }
    __shared__ float wv_[16]; __shared__ int wi_[16];
    __shared__ float wx_[16], wy_[16], wz_[16];
    __shared__ float cval[2][FPS_CL]; __shared__ int cidx[2][FPS_CL];
    __shared__ float cxx[2][FPS_CL], cyy[2][FPS_CL], czz[2][FPS_CL];
    float curx = xp[0], cury = xp[1], curz = xp[2];
    float* orow = out + ((size_t)b * 2048 + 1024) * 3;
    if (rank == 0 && tid == 0) { orow[0]=curx; orow[1]=cury; orow[2]=curz; }

    for (int t = 1; t < 1024; t++) {
        float bv = -1.f; int bi = 0x7fffffff;
        float bx = 0.f, by = 0.f, bz = 0.f;
#pragma unroll
        for (int i = 0; i < 16; i++) {
            float dx = __fsub_rn(px[i], curx), dy = __fsub_rn(py[i], cury), dz = __fsub_rn(pz[i], curz);
            float d = __fadd_rn(__fadd_rn(__fmul_rn(dx,dx), __fmul_rn(dy,dy)), __fmul_rn(dz,dz));
            dd[i] = fminf(dd[i], d);
            int gi = pbase + tid + 512 * i;
            if (dd[i] > bv || (dd[i] == bv && gi < bi)) { bv=dd[i]; bi=gi; bx=px[i]; by=py[i]; bz=pz[i]; }
        }
#pragma unroll
        for (int s = 16; s > 0; s >>= 1) {
            float ov = __shfl_down_sync(0xffffffffu, bv, s);
            int   oi = __shfl_down_sync(0xffffffffu, bi, s);
            float ox = __shfl_down_sync(0xffffffffu, bx, s);
            float oy = __shfl_down_sync(0xffffffffu, by, s);
            float oz = __shfl_down_sync(0xffffffffu, bz, s);
            if (ov > bv || (ov == bv && oi < bi)) { bv=ov; bi=oi; bx=ox; by=oy; bz=oz; }
        }
        if (lane == 0) { wv_[warp]=bv; wi_[warp]=bi; wx_[warp]=bx; wy_[warp]=by; wz_[warp]=bz; }
        __syncthreads();
        int par = t & 1;
        if (warp == 0) {
            bv = (lane < 16) ? wv_[lane] : -1.f;
            bi = (lane < 16) ? wi_[lane] : 0x7fffffff;
            bx = (lane < 16) ? wx_[lane] : 0.f;
            by = (lane < 16) ? wy_[lane] : 0.f;
            bz = (lane < 16) ? wz_[lane] : 0.f;
#pragma unroll
            for (int s = 8; s > 0; s >>= 1) {
                float ov = __shfl_down_sync(0xffffffffu, bv, s);
                int   oi = __shfl_down_sync(0xffffffffu, bi, s);
                float ox = __shfl_down_sync(0xffffffffu, bx, s);
                float oy = __shfl_down_sync(0xffffffffu, by, s);
                float oz = __shfl_down_sync(0xffffffffu, bz, s);
                if (ov > bv || (ov == bv && oi < bi)) { bv=ov; bi=oi; bx=ox; by=oy; bz=oz; }
            }
            if (lane == 0) {
                for (uint32_t r = 0; r < FPS_CL; r++) {
                    stc_f32(smem_u32(&cval[par][rank]), r, bv);
                    stc_u32(smem_u32(&cidx[par][rank]), r, (uint32_t)bi);
                    stc_f32(smem_u32(&cxx[par][rank]), r, bx);
                    stc_f32(smem_u32(&cyy[par][rank]), r, by);
                    stc_f32(smem_u32(&czz[par][rank]), r, bz);
                }
            }
        }
        asm volatile("barrier.cluster.arrive.aligned;" ::: "memory");
        asm volatile("barrier.cluster.wait.aligned;" ::: "memory");
        float vv = cval[par][0]; int vi = cidx[par][0];
        float nx = cxx[par][0], ny = cyy[par][0], nz = czz[par][0];
#pragma unroll
        for (int r = 1; r < FPS_CL; r++) {
            float ov = cval[par][r]; int oi = cidx[par][r];
            if (ov > vv || (ov == vv && oi < vi)) { vv=ov; vi=oi; nx=cxx[par][r]; ny=cyy[par][r]; nz=czz[par][r]; }
        }
        curx = nx; cury = ny; curz = nz;
        if (rank == 0 && tid == 0) { orow[t*3]=nx; orow[t*3+1]=ny; orow[t*3+2]=nz; }
    }
}

// ------------------------- conversion passes -------------------------------
__global__ void conv_plain(const float* __restrict__ S, __nv_bfloat16* __restrict__ H,
                           __nv_bfloat16* __restrict__ L, int nPairs)
{
    int p = blockIdx.x * 256 + threadIdx.x;
    if (p >= nPairs) return;
    float2 v = *(const float2*)(S + (size_t)p * 2);
    __nv_bfloat162 hp, lp;
    hp.x = __float2bfloat16(v.x); hp.y = __float2bfloat16(v.y);
    lp.x = __float2bfloat16(v.x - __bfloat162float(hp.x));
    lp.y = __float2bfloat16(v.y - __bfloat162float(hp.y));
    *(__nv_bfloat162*)(H + (size_t)p * 2) = hp;
    *(__nv_bfloat162*)(L + (size_t)p * 2) = lp;
}
__global__ void conv_bn(const float* __restrict__ raw, const float* __restrict__ sc,
                        const float* __restrict__ sh, __nv_bfloat16* __restrict__ H,
                        __nv_bfloat16* __restrict__ L)
{
    int p = blockIdx.x * 256 + threadIdx.x;   // grid = NBR*MROWS blocks exactly
    int k = (p & 255) * 2, row = p >> 8, z = row >> 14;
    float2 v = *(const float2*)(raw + (size_t)row * 512 + k);
    float a0 = fmaxf(fmaf(v.x, sc[z*512+k],   sh[z*512+k]),   0.f);
    float a1 = fmaxf(fmaf(v.y, sc[z*512+k+1], sh[z*512+k+1]), 0.f);
    __nv_bfloat162 hp, lp;
    hp.x = __float2bfloat16(a0); hp.y = __float2bfloat16(a1);
    lp.x = __float2bfloat16(a0 - __bfloat162float(hp.x));
    lp.y = __float2bfloat16(a1 - __bfloat162float(hp.y));
    *(__nv_bfloat162*)(H + (size_t)row * 512 + k) = hp;
    *(__nv_bfloat162*)(L + (size_t)row * 512 + k) = lp;
}

// -------------- bf16-split tensor-core GEMM, cp.async pipeline -------------
__global__ void __launch_bounds__(256, 1)
gemm_mma2(const __nv_bfloat16* __restrict__ Agh, const __nv_bfloat16* __restrict__ Agl,
          const __nv_bfloat16* __restrict__ Bgh, const __nv_bfloat16* __restrict__ Bgl,
          float* __restrict__ Call, float* __restrict__ psum, float* __restrict__ psq,
          int K, long aStride)
{
    extern __shared__ __align__(16) uint32_t sm[];
    int bx = blockIdx.x, by = blockIdx.y, z = blockIdx.z;
    int tid = threadIdx.x, lane = tid & 31, w = tid >> 5;
    int wm = w & 1, wn = w >> 1;
    int m0 = by * 128, n0 = bx * 128, KC = K >> 5;
    const __nv_bfloat16* Ah = Agh + (size_t)z * aStride;
    const __nv_bfloat16* Al = Agl + (size_t)z * aStride;
    const __nv_bfloat16* Bh = Bgh + (size_t)z * 512 * K;
    const __nv_bfloat16* Bl = Bgl + (size_t)z * 512 * K;
    uint32_t sbase = smem_u32(sm);

    int lr = tid >> 1, half = tid & 1;          // 2 threads per row, 2x16B each
    const __nv_bfloat16* Ar_h = Ah + (size_t)(m0 + lr) * K + half * 16;
    const __nv_bfloat16* Ar_l = Al + (size_t)(m0 + lr) * K + half * 16;
    const __nv_bfloat16* Br_h = Bh + (size_t)(n0 + lr) * K + half * 16;
    const __nv_bfloat16* Br_l = Bl + (size_t)(n0 + lr) * K + half * 16;
    uint32_t drow = lr * 80 + half * 32;

    auto fill = [&](int kc, int s) {
        uint32_t st = sbase + s * 40960;
        int go = kc * 32;
        cpa16(st + drow,                Ar_h + go);
        cpa16(st + drow + 16,           Ar_h + go + 8);
        cpa16(st + 10240 + drow,        Ar_l + go);
        cpa16(st + 10240 + drow + 16,   Ar_l + go + 8);
        cpa16(st + 20480 + drow,        Br_h + go);
        cpa16(st + 20480 + drow + 16,   Br_h + go + 8);
        cpa16(st + 30720 + drow,        Br_l + go);
        cpa16(st + 30720 + drow + 16,   Br_l + go + 8);
    };

    float acc[4][4][4];
#pragma unroll
    for (int i = 0; i < 4; i++)
#pragma unroll
        for (int j = 0; j < 4; j++)
#pragma unroll
            for (int e = 0; e < 4; e++) acc[i][j][e] = 0.f;

    fill(0, 0); CP_COMMIT();
    fill(1, 1); CP_COMMIT();

    int arow = lane & 15, kh = (lane >> 4) * 8;
    int bn_ = ((lane >> 4) & 1) * 8 + (lane & 7), bk = ((lane >> 3) & 1) * 8;

    for (int kc = 0; kc < KC; kc++) {
        int s = kc & 1;
        if (kc + 1 < KC) { CP_WAIT(1); } else { CP_WAIT(0); }
        __syncthreads();
        uint32_t abase = sbase + s * 40960 + (wm * 64) * 80;
        uint32_t bbase = sbase + s * 40960 + 20480 + (wn * 32) * 80;
#pragma unroll
        for (int ks = 0; ks < 2; ks++) {
            uint32_t ah[4][4], alr[4][4], bh[2][4], blr[2][4];
#pragma unroll
            for (int mt = 0; mt < 4; mt++) {
                uint32_t ad = abase + (mt*16 + arow) * 80 + (ks*16 + kh) * 2;
                LDSM4(ah[mt], ad);
                LDSM4(alr[mt], ad + 10240);
            }
#pragma unroll
            for (int g = 0; g < 2; g++) {
                uint32_t bd = bbase + (g*16 + bn_) * 80 + (ks*16 + bk) * 2;
                LDSM4(bh[g], bd);
                LDSM4(blr[g], bd + 10240);
            }
#pragma unroll
            for (int mt = 0; mt < 4; mt++)
#pragma unroll
                for (int nt = 0; nt < 4; nt++) {
                    int g = nt >> 1, p = (nt & 1) * 2;
                    MMA16816(acc[mt][nt], ah[mt],  bh[g][p],  bh[g][p+1]);
                    MMA16816(acc[mt][nt], ah[mt],  blr[g][p], blr[g][p+1]);
                    MMA16816(acc[mt][nt], alr[mt], bh[g][p],  bh[g][p+1]);
                }
        }
        __syncthreads();
        if (kc + 2 < KC) { fill(kc + 2, s); CP_COMMIT(); }
    }

    // epilogue: accum -> smem (pitch 132), stats + coalesced store
    float* cs = (float*)sm;
#pragma unroll
    for (int mt = 0; mt < 4; mt++)
#pragma unroll
        for (int nt = 0; nt < 4; nt++) {
            int r = wm*64 + mt*16 + (lane >> 2);
            int c = wn*32 + nt*8 + (lane & 3) * 2;
            *(float2*)(cs + r*132 + c)     = make_float2(acc[mt][nt][0], acc[mt][nt][1]);
            *(float2*)(cs + (r+8)*132 + c) = make_float2(acc[mt][nt][2], acc[mt][nt][3]);
        }
    __syncthreads();
    if (tid < 128) {
        float s = 0.f, q = 0.f;
#pragma unroll 8
        for (int r = 0; r < 128; r++) { float v = cs[r*132 + tid]; s += v; q = fmaf(v, v, q); }
        size_t ch = (size_t)z * 512 + n0 + tid;
        psum[ch * 128 + by] = s; psq[ch * 128 + by] = q;
    }
    float* C = Call + (size_t)z * MROWS * 512;
#pragma unroll
    for (int i = 0; i < 16; i++) {
        int lin = tid + 256 * i;
        int r = lin >> 5, c4 = (lin & 31) * 4;
        float4 v = *(float4*)(cs + r*132 + c4);
        *(float4*)(C + (size_t)(m0 + r) * 512 + n0 + c4) = v;
    }
}

// --------------------------- SIMT small GEMM (proven) -----------------------
template<int BN, int TN, bool HAS_T, bool HAS_S>
__global__ void __launch_bounds__(256)
gemm_bn(const float* __restrict__ Aall, const float* __restrict__ Wall, float* __restrict__ Call,
        const float* __restrict__ tsc, const float* __restrict__ tsh,
        float* __restrict__ psum, float* __restrict__ psq, int M, int N, int K, long aStride)
{
    constexpr int BM = 128, BK = 8, TM = 8;
    int z = blockIdx.z;
    const float* A = Aall + (size_t)z * (size_t)aStride;
    const float* W = Wall + (size_t)z * N * K;
    float* C = Call + (size_t)z * (size_t)M * N;
    const float* sc = HAS_T ? (tsc + z * K) : nullptr;
    const float* sh = HAS_T ? (tsh + z * K) : nullptr;
    __shared__ float As[BK][BM], Bs[BK][BN], red[16][BN];
    int t = threadIdx.x, m0 = blockIdx.y * BM, n0 = blockIdx.x * BN;
    int tcol = t & 15, trow = t >> 4;
    float acc[TM][TN];
#pragma unroll
    for (int i = 0; i < TM; i++)
#pragma unroll
        for (int j = 0; j < TN; j++) acc[i][j] = 0.f;
    int ar = t >> 1, ac4 = (t & 1) * 4;
    const float* Aload = A + (size_t)(m0 + ar) * K + ac4;
    for (int k0 = 0; k0 < K; k0 += BK) {
        float4 avv = *(const float4*)(Aload + k0);
        if (HAS_T) {
            int c = k0 + ac4;
            avv.x = fmaxf(fmaf(avv.x, sc[c],   sh[c]),   0.f);
            avv.y = fmaxf(fmaf(avv.y, sc[c+1], sh[c+1]), 0.f);
            avv.z = fmaxf(fmaf(avv.z, sc[c+2], sh[c+2]), 0.f);
            avv.w = fmaxf(fmaf(avv.w, sc[c+3], sh[c+3]), 0.f);
        }
        As[ac4][ar] = avv.x; As[ac4+1][ar] = avv.y; As[ac4+2][ar] = avv.z; As[ac4+3][ar] = avv.w;
        for (int e = t; e < BN * 2; e += 256) {
            int wr = e >> 1, wc = (e & 1) * 4;
            float4 wv = *(const float4*)(W + (size_t)(n0 + wr) * K + k0 + wc);
            Bs[wc][wr] = wv.x; Bs[wc+1][wr] = wv.y; Bs[wc+2][wr] = wv.z; Bs[wc+3][wr] = wv.w;
        }
        __syncthreads();
#pragma unroll
        for (int kk = 0; kk < BK; kk++) {
            float a[TM], bb[TN];
            const float4* A4 = (const float4*)(&As[kk][trow * TM]);
            float4 t0 = A4[0], t1 = A4[1];
            a[0]=t0.x; a[1]=t0.y; a[2]=t0.z; a[3]=t0.w; a[4]=t1.x; a[5]=t1.y; a[6]=t1.z; a[7]=t1.w;
            const float4* B4 = (const float4*)(&Bs[kk][tcol * TN]);
            float4 u0 = B4[0];
            bb[0]=u0.x; bb[1]=u0.y; bb[2]=u0.z; bb[3]=u0.w;
            if constexpr (TN == 8) { float4 u1 = B4[1]; bb[4]=u1.x; bb[5]=u1.y; bb[6]=u1.z; bb[7]=u1.w; }
#pragma unroll
            for (int i = 0; i < TM; i++)
#pragma unroll
                for (int j = 0; j < TN; j++) acc[i][j] = fmaf(a[i], bb[j], acc[i][j]);
        }
        __syncthreads();
    }
#pragma unroll
    for (int i = 0; i < TM; i++) {
        float* crow = C + (size_t)(m0 + trow * TM + i) * N + n0 + tcol * TN;
#pragma unroll
        for (int j = 0; j < TN; j += 4)
            *(float4*)(crow + j) = make_float4(acc[i][j], acc[i][j+1], acc[i][j+2], acc[i][j+3]);
    }
    if (HAS_S) {
        float cs2[TN], cq[TN];
#pragma unroll
        for (int j = 0; j < TN; j++) {
            cs2[j] = 0.f; cq[j] = 0.f;
#pragma unroll
            for (int i = 0; i < TM; i++) { cs2[j] += acc[i][j]; cq[j] = fmaf(acc[i][j], acc[i][j], cq[j]); }
        }
#pragma unroll
        for (int j = 0; j < TN; j++) red[trow][tcol * TN + j] = cs2[j];
        __syncthreads();
        for (int s = 8; s > 0; s >>= 1) {
            if (trow < s)
#pragma unroll
                for (int j = 0; j < TN; j++) red[trow][tcol*TN+j] += red[trow+s][tcol*TN+j];
            __syncthreads();
        }
        if (trow == 0)
#pragma unroll
            for (int j = 0; j < TN; j++)
                psum[(size_t)(z * N + n0 + tcol * TN + j) * 128 + blockIdx.y] = red[0][tcol*TN+j];
        __syncthreads();
#pragma unroll
        for (int j = 0; j < TN; j++) red[trow][tcol * TN + j] = cq[j];
        __syncthreads();
        for (int s = 8; s > 0; s >>= 1) {
            if (trow < s)
#pragma unroll
                for (int j = 0; j < TN; j++) red[trow][tcol*TN+j] += red[trow+s][tcol*TN+j];
            __syncthreads();
        }
        if (trow == 0)
#pragma unroll
            for (int j = 0; j < TN; j++)
                psq[(size_t)(z * N + n0 + tcol * TN + j) * 128 + blockIdx.y] = red[0][tcol*TN+j];
    }
}

__global__ void bn_finalize(const float* __restrict__ psum, const float* __restrict__ psq,
                            const float* __restrict__ gam, const float* __restrict__ bet,
                            float* __restrict__ sc, float* __restrict__ sh, int total)
{
    int i = blockIdx.x * blockDim.x + threadIdx.x;
    if (i >= total) return;
    float s = 0.f, q = 0.f;
    const float* ps = psum + (size_t)i * 128;
    const float* pq = psq + (size_t)i * 128;
#pragma unroll 8
    for (int k = 0; k < 128; k++) { s += ps[k]; q += pq[k]; }
    float mean = s * (1.f / 16384.f);
    float var = fmaf(-mean, mean, q * (1.f / 16384.f));
    float g = gam[i] * rsqrtf(var + BN_EPS);
    sc[i] = g; sh[i] = fmaf(-mean, g, bet[i]);
}

// ----------------------------- softmax/pool (proven) ------------------------
__global__ void __launch_bounds__(256, 1)
softmax_pts_kernel(const float* __restrict__ t3, const float* __restrict__ h4raw,
                   const float* __restrict__ scaleL, const float* __restrict__ shiftL,
                   const float* __restrict__ aW4, const float* __restrict__ ab4,
                   float* __restrict__ out)
{
    int b = blockIdx.x, n = blockIdx.y;
    extern __shared__ float base_sh[];
    __shared__ float w4[3][64], b4[3];
    int tid = threadIdx.x;
    if (tid < 192) w4[tid / 64][tid % 64] = aW4[n * 192 + tid];
    if (tid < 3) b4[tid] = ab4[n * 3 + tid];
    const float* sc = scaleL + n * 64;
    const float* sh = shiftL + n * 64;
    const float* h4b = h4raw + ((size_t)n * MROWS + b * 512) * 64;
    for (int i = tid; i < 512 * 64; i += 256) {
        int l = i >> 6, k = i & 63;
        base_sh[l * 65 + k] = fmaxf(fmaf(h4b[i], sc[k], sh[k]), 0.f);
    }
    __syncthreads();
    int lane = tid & 31, warp = tid >> 5;
    const float* t3b = t3 + ((size_t)n * MROWS + b * 512) * 128;
    float* orow = out + ((size_t)b * 2048 + n * 128) * 3;
    for (int c = 0; c < 16; c++) {
        int m = warp + c * 8;
        float v[16], mx = -1e30f;
#pragma unroll
        for (int i = 0; i < 16; i++) { v[i] = t3b[(size_t)(lane + 32*i) * 128 + m]; mx = fmaxf(mx, v[i]); }
#pragma unroll
        for (int s = 16; s > 0; s >>= 1) mx = fmaxf(mx, __shfl_xor_sync(0xffffffffu, mx, s));
        float sum = 0.f;
#pragma unroll
        for (int i = 0; i < 16; i++) { v[i] = expf(v[i] - mx); sum += v[i]; }
#pragma unroll
        for (int s = 16; s > 0; s >>= 1) sum += __shfl_xor_sync(0xffffffffu, sum, s);
        float inv = 1.f / sum;
#pragma unroll
        for (int i = 0; i < 16; i++) v[i] *= inv;
        float o0 = 0.f, o1 = 0.f, o2 = 0.f;
        for (int k = 0; k < 64; k++) {
            float p = 0.f;
#pragma unroll
            for (int i = 0; i < 16; i++) p = fmaf(v[i], base_sh[(lane + 32*i) * 65 + k], p);
#pragma unroll
            for (int s = 16; s > 0; s >>= 1) p += __shfl_xor_sync(0xffffffffu, p, s);
            o0 = fmaf(w4[0][k], p, o0); o1 = fmaf(w4[1][k], p, o1); o2 = fmaf(w4[2][k], p, o2);
        }
        if (lane == 0) { orow[m*3] = o0 + b4[0]; orow[m*3+1] = o1 + b4[1]; orow[m*3+2] = o2 + b4[2]; }
    }
}

// ------------------------------- launch ------------------------------------
extern "C" void kernel_launch(void* const* d_in, const int* in_sizes, int n_in,
                              void* d_out, int out_size)
{
    (void)in_sizes; (void)n_in; (void)out_size;
    const float* x     = (const float*)d_in[0];
    const float* xpart = (const float*)d_in[1];
    const float* mW1 = (const float*)d_in[2];
    const float* mg1 = (const float*)d_in[4];
    const float* mB1 = (const float*)d_in[5];
    const float* mW2 = (const float*)d_in[6];
    const float* mg2 = (const float*)d_in[8];
    const float* mB2 = (const float*)d_in[9];
    const float* mW3 = (const float*)d_in[10];
    const float* mg3 = (const float*)d_in[12];
    const float* mB3 = (const float*)d_in[13];
    const float* mW4 = (const float*)d_in[14];
    const float* mg4 = (const float*)d_in[16];
    const float* mB4 = (const float*)d_in[17];
    const float* aW1 = (const float*)d_in[18];
    const float* ag1 = (const float*)d_in[20];
    const float* aB1 = (const float*)d_in[21];
    const float* aW2 = (const float*)d_in[22];
    const float* ag2 = (const float*)d_in[24];
    const float* aB2 = (const float*)d_in[25];
    const float* aW3 = (const float*)d_in[26];
    const float* aW4 = (const float*)d_in[28];
    const float* ab4 = (const float*)d_in[29];
    float* out = (float*)d_out;

    float *bufA, *bufB, *h4, *t1, *t2, *t3, *psum, *psq, *sc, *sh;
    __nv_bfloat16 *Ahp, *Alp, *Xh, *Xl, *W1h, *W1l, *W2h, *W2l, *W3h, *W3l;
    cudaGetSymbolAddress((void**)&bufA, g_bufA);
    cudaGetSymbolAddress((void**)&bufB, g_bufB);
    cudaGetSymbolAddress((void**)&h4, g_h4);
    cudaGetSymbolAddress((void**)&t1, g_t1);
    cudaGetSymbolAddress((void**)&t2, g_t2);
    cudaGetSymbolAddress((void**)&t3, g_t3);
    cudaGetSymbolAddress((void**)&psum, g_psum);
    cudaGetSymbolAddress((void**)&psq, g_psq);
    cudaGetSymbolAddress((void**)&sc, g_scale);
    cudaGetSymbolAddress((void**)&sh, g_shift);
    cudaGetSymbolAddress((void**)&Ahp, g_Ah);
    cudaGetSymbolAddress((void**)&Alp, g_Al);
    cudaGetSymbolAddress((void**)&Xh, g_Xh);
    cudaGetSymbolAddress((void**)&Xl, g_Xl);
    cudaGetSymbolAddress((void**)&W1h, g_W1h);
    cudaGetSymbolAddress((void**)&W1l, g_W1l);
    cudaGetSymbolAddress((void**)&W2h, g_W2h);
    cudaGetSymbolAddress((void**)&W2l, g_W2l);
    cudaGetSymbolAddress((void**)&W3h, g_W3h);
    cudaGetSymbolAddress((void**)&W3l, g_W3l);

    static bool attr_done = false;
    if (!attr_done) {
        cudaFuncSetAttribute(softmax_pts_kernel, cudaFuncAttributeMaxDynamicSharedMemorySize, 512 * 65 * 4);
        cudaFuncSetAttribute(gemm_mma2, cudaFuncAttributeMaxDynamicSharedMemorySize, 81920);
        attr_done = true;
    }

    const int SL = NBR * 512;
    const long MS512 = (long)MROWS * 512;
    const long MS64  = (long)MROWS * 64;
    const long MS128 = (long)MROWS * 128;

    fps_kernel<<<32 * FPS_CL, 512>>>(xpart, out);

    conv_plain<<<(NBR*512*128)/256, 256>>>(mW1, W1h, W1l, NBR*512*128);
    conv_plain<<<(NBR*512*256)/256, 256>>>(mW2, W2h, W2l, NBR*512*256);
    conv_plain<<<(NBR*512*256)/256, 256>>>(mW3, W3h, W3l, NBR*512*256);
    conv_plain<<<(MROWS*128)/256, 256>>>(x, Xh, Xl, MROWS*128);

    gemm_mma2<<<dim3(4, 128, NBR), 256, 81920>>>(Xh, Xl, W1h, W1l, bufA, psum, psq, 256, 0);
    bn_finalize<<<16, 256>>>(psum, psq, mg1, mB1, sc, sh, NBR * 512);

    conv_bn<<<NBR * MROWS, 256>>>(bufA, sc, sh, Ahp, Alp);
    gemm_mma2<<<dim3(4, 128, NBR), 256, 81920>>>(Ahp, Alp, W2h, W2l, bufB, psum, psq, 512, MS512);
    bn_finalize<<<16, 256>>>(psum, psq, mg2, mB2, sc + SL, sh + SL, NBR * 512);

    conv_bn<<<NBR * MROWS, 256>>>(bufB, sc + SL, sh + SL, Ahp, Alp);
    gemm_mma2<<<dim3(4, 128, NBR), 256, 81920>>>(Ahp, Alp, W3h, W3l, bufA, psum, psq, 512, MS512);
    bn_finalize<<<16, 256>>>(psum, psq, mg3, mB3, sc + 2 * SL, sh + 2 * SL, NBR * 512);

    gemm_bn<64, 4, true, true><<<dim3(1, 128, NBR), 256>>>(
        bufA, mW4, h4, sc + 2 * SL, sh + 2 * SL, psum, psq, MROWS, 64, 512, MS512);
    bn_finalize<<<2, 256>>>(psum, psq, mg4, mB4, sc + 3 * SL, sh + 3 * SL, NBR * 64);

    gemm_bn<64, 4, true, true><<<dim3(1, 128, NBR), 256>>>(
        h4, aW1, t1, sc + 3 * SL, sh + 3 * SL, psum, psq, MROWS, 64, 64, MS64);
    bn_finalize<<<2, 256>>>(psum, psq, ag1, aB1, sc + 4 * SL, sh + 4 * SL, NBR * 64);

    gemm_bn<128, 8, true, true><<<dim3(1, 128, NBR), 256>>>(
        t1, aW2, t2, sc + 4 * SL, sh + 4 * SL, psum, psq, MROWS, 128, 64, MS64);
    bn_finalize<<<4, 256>>>(psum, psq, ag2, aB2, sc + 5 * SL, sh + 5 * SL, NBR * 128);

    gemm_bn<128, 8, true, false><<<dim3(1, 128, NBR), 256>>>(
        t2, aW3, t3, sc + 5 * SL, sh + 5 * SL, nullptr, nullptr, MROWS, 128, 128, MS128);

    softmax_pts_kernel<<<dim3(32, NBR), 256, 512 * 65 * 4>>>(
        t3, h4, sc + 3 * SL, sh + 3 * SL, aW4, ab4, out);
}

// round 7
// speedup vs baseline: 2.5103x; 1.0422x over previous
#include <cuda_runtime.h>
#include <cuda_bf16.h>
#include <cstdint>
#include <cstddef>

#define NBR 8
#define MROWS 16384
#define BN_EPS 1e-5f

__device__ __align__(256) float g_bufA[(size_t)NBR * MROWS * 512];
__device__ __align__(256) float g_bufB[(size_t)NBR * MROWS * 512];
__device__ __align__(256) float g_h4 [(size_t)NBR * MROWS * 64];
__device__ __align__(256) float g_t1 [(size_t)NBR * MROWS * 64];
__device__ __align__(256) float g_t2 [(size_t)NBR * MROWS * 128];
__device__ __align__(256) float g_t3 [(size_t)NBR * MROWS * 128];
__device__ float g_psum [NBR * 512 * 128];
__device__ float g_psq  [NBR * 512 * 128];
__device__ float g_scale[6 * NBR * 512];
__device__ float g_shift[6 * NBR * 512];
__device__ __align__(16) __nv_bfloat16 g_Ah[(size_t)NBR * MROWS * 512];
__device__ __align__(16) __nv_bfloat16 g_Al[(size_t)NBR * MROWS * 512];
__device__ __align__(16) __nv_bfloat16 g_Xh[(size_t)MROWS * 256];
__device__ __align__(16) __nv_bfloat16 g_Xl[(size_t)MROWS * 256];
__device__ __align__(16) __nv_bfloat16 g_W1h[NBR * 512 * 256];
__device__ __align__(16) __nv_bfloat16 g_W1l[NBR * 512 * 256];
__device__ __align__(16) __nv_bfloat16 g_W2h[NBR * 512 * 512];
__device__ __align__(16) __nv_bfloat16 g_W2l[NBR * 512 * 512];
__device__ __align__(16) __nv_bfloat16 g_W3h[NBR * 512 * 512];
__device__ __align__(16) __nv_bfloat16 g_W3l[NBR * 512 * 512];
__device__ __align__(16) __nv_bfloat16 g_W4h[NBR * 128 * 512];   // padded 64->128 rows
__device__ __align__(16) __nv_bfloat16 g_W4l[NBR * 128 * 512];

__device__ __forceinline__ uint32_t smem_u32(const void* p) {
    uint32_t a;
    asm("{ .reg .u64 t; cvta.to.shared.u64 t, %1; cvt.u32.u64 %0, t; }" : "=r"(a) : "l"(p));
    return a;
}
__device__ __forceinline__ void stc_f32(uint32_t sa, uint32_t rank, float v) {
    uint32_t r;
    asm volatile("mapa.shared::cluster.u32 %0, %1, %2;" : "=r"(r) : "r"(sa), "r"(rank));
    asm volatile("st.shared::cluster.f32 [%0], %1;" :: "r"(r), "f"(v) : "memory");
}
__device__ __forceinline__ void stc_u32(uint32_t sa, uint32_t rank, uint32_t v) {
    uint32_t r;
    asm volatile("mapa.shared::cluster.u32 %0, %1, %2;" : "=r"(r) : "r"(sa), "r"(rank));
    asm volatile("st.shared::cluster.u32 [%0], %1;" :: "r"(r), "r"(v) : "memory");
}
__device__ __forceinline__ void cpa16(uint32_t d, const void* g) {
    asm volatile("cp.async.cg.shared.global [%0], [%1], 16;" :: "r"(d), "l"(g));
}
#define CP_COMMIT() asm volatile("cp.async.commit_group;")
#define CP_WAIT(N)  asm volatile("cp.async.wait_group %0;" :: "n"(N))
#define LDSM4(R, ADDR) \
    asm volatile("ldmatrix.sync.aligned.m8n8.x4.shared.b16 {%0,%1,%2,%3}, [%4];" \
        : "=r"((R)[0]), "=r"((R)[1]), "=r"((R)[2]), "=r"((R)[3]) : "r"(ADDR))
#define MMA16816(D, A, B0, B1) \
    asm volatile("mma.sync.aligned.m16n8k16.row.col.f32.bf16.bf16.f32 " \
        "{%0,%1,%2,%3}, {%4,%5,%6,%7}, {%8,%9}, {%0,%1,%2,%3};" \
        : "+f"((D)[0]), "+f"((D)[1]), "+f"((D)[2]), "+f"((D)[3]) \
        : "r"((A)[0]), "r"((A)[1]), "r"((A)[2]), "r"((A)[3]), "r"(B0), "r"(B1))

// ------------------------------ FPS (proven) --------------------------------
#define FPS_CL 4
__global__ void __cluster_dims__(FPS_CL,1,1) __launch_bounds__(512,1)
fps_kernel(const float* __restrict__ xpart, float* __restrict__ out)
{
    uint32_t rank; asm("mov.u32 %0, %%cluster_ctarank;" : "=r"(rank));
    int b = blockIdx.x / FPS_CL;
    const float* xp = xpart + (size_t)b * 32768 * 3;
    int tid = threadIdx.x, lane = tid & 31, warp = tid >> 5;
    int pbase = (int)rank * 8192;
    float px[16], py[16], pz[16], dd[16];
#pragma unroll
    for (int i = 0; i < 16; i++) {
        int p = pbase + tid + 512 * i;
        px[i] = xp[p*3]; py[i] = xp[p*3+1]; pz[i] = xp[p*3+2]; dd[i] = 1e10f;
    }
    __shared__ float wv_[16]; __shared__ int wi_[16];
    __shared__ float wx_[16], wy_[16], wz_[16];
    __shared__ float cval[2][FPS_CL]; __shared__ int cidx[2][FPS_CL];
    __shared__ float cxx[2][FPS_CL], cyy[2][FPS_CL], czz[2][FPS_CL];
    float curx = xp[0], cury = xp[1], curz = xp[2];
    float* orow = out + ((size_t)b * 2048 + 1024) * 3;
    if (rank == 0 && tid == 0) { orow[0]=curx; orow[1]=cury; orow[2]=curz; }

    for (int t = 1; t < 1024; t++) {
        float bv = -1.f; int bi = 0x7fffffff;
        float bx = 0.f, by = 0.f, bz = 0.f;
#pragma unroll
        for (int i = 0; i < 16; i++) {
            float dx = __fsub_rn(px[i], curx), dy = __fsub_rn(py[i], cury), dz = __fsub_rn(pz[i], curz);
            float d = __fadd_rn(__fadd_rn(__fmul_rn(dx,dx), __fmul_rn(dy,dy)), __fmul_rn(dz,dz));
            dd[i] = fminf(dd[i], d);
            int gi = pbase + tid + 512 * i;
            if (dd[i] > bv || (dd[i] == bv && gi < bi)) { bv=dd[i]; bi=gi; bx=px[i]; by=py[i]; bz=pz[i]; }
        }
#pragma unroll
        for (int s = 16; s > 0; s >>= 1) {
            float ov = __shfl_down_sync(0xffffffffu, bv, s);
            int   oi = __shfl_down_sync(0xffffffffu, bi, s);
            float ox = __shfl_down_sync(0xffffffffu, bx, s);
            float oy = __shfl_down_sync(0xffffffffu, by, s);
            float oz = __shfl_down_sync(0xffffffffu, bz, s);
            if (ov > bv || (ov == bv && oi < bi)) { bv=ov; bi=oi; bx=ox; by=oy; bz=oz; }
        }
        if (lane == 0) { wv_[warp]=bv; wi_[warp]=bi; wx_[warp]=bx; wy_[warp]=by; wz_[warp]=bz; }
        __syncthreads();
        int par = t & 1;
        if (warp == 0) {
            bv = (lane < 16) ? wv_[lane] : -1.f;
            bi = (lane < 16) ? wi_[lane] : 0x7fffffff;
            bx = (lane < 16) ? wx_[lane] : 0.f;
            by = (lane < 16) ? wy_[lane] : 0.f;
            bz = (lane < 16) ? wz_[lane] : 0.f;
#pragma unroll
            for (int s = 8; s > 0; s >>= 1) {
                float ov = __shfl_down_sync(0xffffffffu, bv, s);
                int   oi = __shfl_down_sync(0xffffffffu, bi, s);
                float ox = __shfl_down_sync(0xffffffffu, bx, s);
                float oy = __shfl_down_sync(0xffffffffu, by, s);
                float oz = __shfl_down_sync(0xffffffffu, bz, s);
                if (ov > bv || (ov == bv && oi < bi)) { bv=ov; bi=oi; bx=ox; by=oy; bz=oz; }
            }
            if (lane == 0) {
                for (uint32_t r = 0; r < FPS_CL; r++) {
                    stc_f32(smem_u32(&cval[par][rank]), r, bv);
                    stc_u32(smem_u32(&cidx[par][rank]), r, (uint32_t)bi);
                    stc_f32(smem_u32(&cxx[par][rank]), r, bx);
                    stc_f32(smem_u32(&cyy[par][rank]), r, by);
                    stc_f32(smem_u32(&czz[par][rank]), r, bz);
                }
            }
        }
        asm volatile("barrier.cluster.arrive.aligned;" ::: "memory");
        asm volatile("barrier.cluster.wait.aligned;" ::: "memory");
        float vv = cval[par][0]; int vi = cidx[par][0];
        float nx = cxx[par][0], ny = cyy[par][0], nz = czz[par][0];
#pragma unroll
        for (int r = 1; r < FPS_CL; r++) {
            float ov = cval[par][r]; int oi = cidx[par][r];
            if (ov > vv || (ov == vv && oi < vi)) { vv=ov; vi=oi; nx=cxx[par][r]; ny=cyy[par][r]; nz=czz[par][r]; }
        }
        curx = nx; cury = ny; curz = nz;
        if (rank == 0 && tid == 0) { orow[t*3]=nx; orow[t*3+1]=ny; orow[t*3+2]=nz; }
    }
}

// ------------------------- conversion passes -------------------------------
__global__ void conv_plain(const float* __restrict__ S, __nv_bfloat16* __restrict__ H,
                           __nv_bfloat16* __restrict__ L, int nPairs)
{
    int p = blockIdx.x * 256 + threadIdx.x;
    if (p >= nPairs) return;
    float2 v = *(const float2*)(S + (size_t)p * 2);
    __nv_bfloat162 hp, lp;
    hp.x = __float2bfloat16(v.x); hp.y = __float2bfloat16(v.y);
    lp.x = __float2bfloat16(v.x - __bfloat162float(hp.x));
    lp.y = __float2bfloat16(v.y - __bfloat162float(hp.y));
    *(__nv_bfloat162*)(H + (size_t)p * 2) = hp;
    *(__nv_bfloat162*)(L + (size_t)p * 2) = lp;
}
// mW4 [NBR][64][512] -> padded [NBR][128][512] hi/lo (rows 64..127 zero)
__global__ void conv_w4(const float* __restrict__ S, __nv_bfloat16* __restrict__ H,
                        __nv_bfloat16* __restrict__ L)
{
    int p = blockIdx.x * 256 + threadIdx.x;        // pair index over NBR*128*256
    if (p >= NBR * 128 * 256) return;
    int k2 = p & 255, rem = p >> 8, n = rem & 127, z = rem >> 7;
    __nv_bfloat162 hp, lp;
    if (n < 64) {
        float2 v = *(const float2*)(S + (((size_t)z * 64 + n) * 512) + k2 * 2);
        hp.x = __float2bfloat16(v.x); hp.y = __float2bfloat16(v.y);
        lp.x = __float2bfloat16(v.x - __bfloat162float(hp.x));
        lp.y = __float2bfloat16(v.y - __bfloat162float(hp.y));
    } else {
        hp.x = hp.y = lp.x = lp.y = __float2bfloat16(0.f);
    }
    *(__nv_bfloat162*)(H + (size_t)p * 2) = hp;
    *(__nv_bfloat162*)(L + (size_t)p * 2) = lp;
}
__global__ void conv_bn(const float* __restrict__ raw, const float* __restrict__ sc,
                        const float* __restrict__ sh, __nv_bfloat16* __restrict__ H,
                        __nv_bfloat16* __restrict__ L)
{
    int p = blockIdx.x * 256 + threadIdx.x;
    int k = (p & 255) * 2, row = p >> 8, z = row >> 14;
    float2 v = *(const float2*)(raw + (size_t)row * 512 + k);
    float a0 = fmaxf(fmaf(v.x, sc[z*512+k],   sh[z*512+k]),   0.f);
    float a1 = fmaxf(fmaf(v.y, sc[z*512+k+1], sh[z*512+k+1]), 0.f);
    __nv_bfloat162 hp, lp;
    hp.x = __float2bfloat16(a0); hp.y = __float2bfloat16(a1);
    lp.x = __float2bfloat16(a0 - __bfloat162float(hp.x));
    lp.y = __float2bfloat16(a1 - __bfloat162float(hp.y));
    *(__nv_bfloat162*)(H + (size_t)row * 512 + k) = hp;
    *(__nv_bfloat162*)(L + (size_t)row * 512 + k) = lp;
}

// -------------- bf16-split tensor-core GEMM, cp.async pipeline -------------
__global__ void __launch_bounds__(256, 1)
gemm_mma2(const __nv_bfloat16* __restrict__ Agh, const __nv_bfloat16* __restrict__ Agl,
          const __nv_bfloat16* __restrict__ Bgh, const __nv_bfloat16* __restrict__ Bgl,
          float* __restrict__ Call, float* __restrict__ psum, float* __restrict__ psq,
          int K, long aStride, long bStride, int Nout)
{
    extern __shared__ __align__(16) uint32_t sm[];
    int bx = blockIdx.x, by = blockIdx.y, z = blockIdx.z;
    int tid = threadIdx.x, lane = tid & 31, w = tid >> 5;
    int wm = w & 1, wn = w >> 1;
    int m0 = by * 128, n0 = bx * 128, KC = K >> 5;
    const __nv_bfloat16* Ah = Agh + (size_t)z * aStride;
    const __nv_bfloat16* Al = Agl + (size_t)z * aStride;
    const __nv_bfloat16* Bh = Bgh + (size_t)z * bStride;
    const __nv_bfloat16* Bl = Bgl + (size_t)z * bStride;
    uint32_t sbase = smem_u32(sm);

    int lr = tid >> 1, half = tid & 1;
    const __nv_bfloat16* Ar_h = Ah + (size_t)(m0 + lr) * K + half * 16;
    const __nv_bfloat16* Ar_l = Al + (size_t)(m0 + lr) * K + half * 16;
    const __nv_bfloat16* Br_h = Bh + (size_t)(n0 + lr) * K + half * 16;
    const __nv_bfloat16* Br_l = Bl + (size_t)(n0 + lr) * K + half * 16;
    uint32_t drow = lr * 80 + half * 32;

    auto fill = [&](int kc, int s) {
        uint32_t st = sbase + s * 40960;
        int go = kc * 32;
        cpa16(st + drow,                Ar_h + go);
        cpa16(st + drow + 16,           Ar_h + go + 8);
        cpa16(st + 10240 + drow,        Ar_l + go);
        cpa16(st + 10240 + drow + 16,   Ar_l + go + 8);
        cpa16(st + 20480 + drow,        Br_h + go);
        cpa16(st + 20480 + drow + 16,   Br_h + go + 8);
        cpa16(st + 30720 + drow,        Br_l + go);
        cpa16(st + 30720 + drow + 16,   Br_l + go + 8);
    };

    float acc[4][4][4];
#pragma unroll
    for (int i = 0; i < 4; i++)
#pragma unroll
        for (int j = 0; j < 4; j++)
#pragma unroll
            for (int e = 0; e < 4; e++) acc[i][j][e] = 0.f;

    fill(0, 0); CP_COMMIT();
    fill(1, 1); CP_COMMIT();

    int arow = lane & 15, kh = (lane >> 4) * 8;
    int bn_ = ((lane >> 4) & 1) * 8 + (lane & 7), bk = ((lane >> 3) & 1) * 8;

    for (int kc = 0; kc < KC; kc++) {
        int s = kc & 1;
        if (kc + 1 < KC) { CP_WAIT(1); } else { CP_WAIT(0); }
        __syncthreads();
        uint32_t abase = sbase + s * 40960 + (wm * 64) * 80;
        uint32_t bbase = sbase + s * 40960 + 20480 + (wn * 32) * 80;
#pragma unroll
        for (int ks = 0; ks < 2; ks++) {
            uint32_t ah[4][4], alr[4][4], bh[2][4], blr[2][4];
#pragma unroll
            for (int mt = 0; mt < 4; mt++) {
                uint32_t ad = abase + (mt*16 + arow) * 80 + (ks*16 + kh) * 2;
                LDSM4(ah[mt], ad);
                LDSM4(alr[mt], ad + 10240);
            }
#pragma unroll
            for (int g = 0; g < 2; g++) {
                uint32_t bd = bbase + (g*16 + bn_) * 80 + (ks*16 + bk) * 2;
                LDSM4(bh[g], bd);
                LDSM4(blr[g], bd + 10240);
            }
#pragma unroll
            for (int mt = 0; mt < 4; mt++)
#pragma unroll
                for (int nt = 0; nt < 4; nt++) {
                    int g = nt >> 1, p = (nt & 1) * 2;
                    MMA16816(acc[mt][nt], ah[mt],  bh[g][p],  bh[g][p+1]);
                    MMA16816(acc[mt][nt], ah[mt],  blr[g][p], blr[g][p+1]);
                    MMA16816(acc[mt][nt], alr[mt], bh[g][p],  bh[g][p+1]);
                }
        }
        __syncthreads();
        if (kc + 2 < KC) { fill(kc + 2, s); CP_COMMIT(); }
    }

    // epilogue
    float* cs = (float*)sm;
#pragma unroll
    for (int mt = 0; mt < 4; mt++)
#pragma unroll
        for (int nt = 0; nt < 4; nt++) {
            int r = wm*64 + mt*16 + (lane >> 2);
            int c = wn*32 + nt*8 + (lane & 3) * 2;
            *(float2*)(cs + r*132 + c)     = make_float2(acc[mt][nt][0], acc[mt][nt][1]);
            *(float2*)(cs + (r+8)*132 + c) = make_float2(acc[mt][nt][2], acc[mt][nt][3]);
        }
    __syncthreads();
    if (tid < 128 && n0 + tid < Nout) {
        float s = 0.f, q = 0.f;
#pragma unroll 8
        for (int r = 0; r < 128; r++) { float v = cs[r*132 + tid]; s += v; q = fmaf(v, v, q); }
        size_t ch = (size_t)z * Nout + n0 + tid;
        psum[ch * 128 + by] = s; psq[ch * 128 + by] = q;
    }
    float* C = Call + (size_t)z * MROWS * Nout;
#pragma unroll
    for (int i = 0; i < 16; i++) {
        int lin = tid + 256 * i;
        int r = lin >> 5, c4 = (lin & 31) * 4;
        if (n0 + c4 < Nout) {
            float4 v = *(float4*)(cs + r*132 + c4);
            *(float4*)(C + (size_t)(m0 + r) * Nout + n0 + c4) = v;
        }
    }
}

// --------------------------- SIMT small GEMM (proven) -----------------------
template<int BN, int TN, bool HAS_T, bool HAS_S>
__global__ void __launch_bounds__(256)
gemm_bn(const float* __restrict__ Aall, const float* __restrict__ Wall, float* __restrict__ Call,
        const float* __restrict__ tsc, const float* __restrict__ tsh,
        float* __restrict__ psum, float* __restrict__ psq, int M, int N, int K, long aStride)
{
    constexpr int BM = 128, BK = 8, TM = 8;
    int z = blockIdx.z;
    const float* A = Aall + (size_t)z * (size_t)aStride;
    const float* W = Wall + (size_t)z * N * K;
    float* C = Call + (size_t)z * (size_t)M * N;
    const float* sc = HAS_T ? (tsc + z * K) : nullptr;
    const float* sh = HAS_T ? (tsh + z * K) : nullptr;
    __shared__ float As[BK][BM], Bs[BK][BN], red[16][BN];
    int t = threadIdx.x, m0 = blockIdx.y * BM, n0 = blockIdx.x * BN;
    int tcol = t & 15, trow = t >> 4;
    float acc[TM][TN];
#pragma unroll
    for (int i = 0; i < TM; i++)
#pragma unroll
        for (int j = 0; j < TN; j++) acc[i][j] = 0.f;
    int ar = t >> 1, ac4 = (t & 1) * 4;
    const float* Aload = A + (size_t)(m0 + ar) * K + ac4;
    for (int k0 = 0; k0 < K; k0 += BK) {
        float4 avv = *(const float4*)(Aload + k0);
        if (HAS_T) {
            int c = k0 + ac4;
            avv.x = fmaxf(fmaf(avv.x, sc[c],   sh[c]),   0.f);
            avv.y = fmaxf(fmaf(avv.y, sc[c+1], sh[c+1]), 0.f);
            avv.z = fmaxf(fmaf(avv.z, sc[c+2], sh[c+2]), 0.f);
            avv.w = fmaxf(fmaf(avv.w, sc[c+3], sh[c+3]), 0.f);
        }
        As[ac4][ar] = avv.x; As[ac4+1][ar] = avv.y; As[ac4+2][ar] = avv.z; As[ac4+3][ar] = avv.w;
        for (int e = t; e < BN * 2; e += 256) {
            int wr = e >> 1, wc = (e & 1) * 4;
            float4 wv = *(const float4*)(W + (size_t)(n0 + wr) * K + k0 + wc);
            Bs[wc][wr] = wv.x; Bs[wc+1][wr] = wv.y; Bs[wc+2][wr] = wv.z; Bs[wc+3][wr] = wv.w;
        }
        __syncthreads();
#pragma unroll
        for (int kk = 0; kk < BK; kk++) {
            float a[TM], bb[TN];
            const float4* A4 = (const float4*)(&As[kk][trow * TM]);
            float4 t0 = A4[0], t1 = A4[1];
            a[0]=t0.x; a[1]=t0.y; a[2]=t0.z; a[3]=t0.w; a[4]=t1.x; a[5]=t1.y; a[6]=t1.z; a[7]=t1.w;
            const float4* B4 = (const float4*)(&Bs[kk][tcol * TN]);
            float4 u0 = B4[0];
            bb[0]=u0.x; bb[1]=u0.y; bb[2]=u0.z; bb[3]=u0.w;
            if constexpr (TN == 8) { float4 u1 = B4[1]; bb[4]=u1.x; bb[5]=u1.y; bb[6]=u1.z; bb[7]=u1.w; }
#pragma unroll
            for (int i = 0; i < TM; i++)
#pragma unroll
                for (int j = 0; j < TN; j++) acc[i][j] = fmaf(a[i], bb[j], acc[i][j]);
        }
        __syncthreads();
    }
#pragma unroll
    for (int i = 0; i < TM; i++) {
        float* crow = C + (size_t)(m0 + trow * TM + i) * N + n0 + tcol * TN;
#pragma unroll
        for (int j = 0; j < TN; j += 4)
            *(float4*)(crow + j) = make_float4(acc[i][j], acc[i][j+1], acc[i][j+2], acc[i][j+3]);
    }
    if (HAS_S) {
        float cs2[TN], cq[TN];
#pragma unroll
        for (int j = 0; j < TN; j++) {
            cs2[j] = 0.f; cq[j] = 0.f;
#pragma unroll
            for (int i = 0; i < TM; i++) { cs2[j] += acc[i][j]; cq[j] = fmaf(acc[i][j], acc[i][j], cq[j]); }
        }
#pragma unroll
        for (int j = 0; j < TN; j++) red[trow][tcol * TN + j] = cs2[j];
        __syncthreads();
        for (int s = 8; s > 0; s >>= 1) {
            if (trow < s)
#pragma unroll
                for (int j = 0; j < TN; j++) red[trow][tcol*TN+j] += red[trow+s][tcol*TN+j];
            __syncthreads();
        }
        if (trow == 0)
#pragma unroll
            for (int j = 0; j < TN; j++)
                psum[(size_t)(z * N + n0 + tcol * TN + j) * 128 + blockIdx.y] = red[0][tcol*TN+j];
        __syncthreads();
#pragma unroll
        for (int j = 0; j < TN; j++) red[trow][tcol * TN + j] = cq[j];
        __syncthreads();
        for (int s = 8; s > 0; s >>= 1) {
            if (trow < s)
#pragma unroll
                for (int j = 0; j < TN; j++) red[trow][tcol*TN+j] += red[trow+s][tcol*TN+j];
            __syncthreads();
        }
        if (trow == 0)
#pragma unroll
            for (int j = 0; j < TN; j++)
                psq[(size_t)(z * N + n0 + tcol * TN + j) * 128 + blockIdx.y] = red[0][tcol*TN+j];
    }
}

__global__ void bn_finalize(const float* __restrict__ psum, const float* __restrict__ psq,
                            const float* __restrict__ gam, const float* __restrict__ bet,
                            float* __restrict__ sc, float* __restrict__ sh, int total)
{
    int i = blockIdx.x * blockDim.x + threadIdx.x;
    if (i >= total) return;
    float s = 0.f, q = 0.f;
    const float* ps = psum + (size_t)i * 128;
    const float* pq = psq + (size_t)i * 128;
#pragma unroll 8
    for (int k = 0; k < 128; k++) { s += ps[k]; q += pq[k]; }
    float mean = s * (1.f / 16384.f);
    float var = fmaf(-mean, mean, q * (1.f / 16384.f));
    float g = gam[i] * rsqrtf(var + BN_EPS);
    sc[i] = g; sh[i] = fmaf(-mean, g, bet[i]);
}

// ----------------------------- softmax/pool (proven) ------------------------
__global__ void __launch_bounds__(256, 1)
softmax_pts_kernel(const float* __restrict__ t3, const float* __restrict__ h4raw,
                   const float* __restrict__ scaleL, const float* __restrict__ shiftL,
                   const float* __restrict__ aW4, const float* __restrict__ ab4,
                   float* __restrict__ out)
{
    int b = blockIdx.x, n = blockIdx.y;
    extern __shared__ float base_sh[];
    __shared__ float w4[3][64], b4[3];
    int tid = threadIdx.x;
    if (tid < 192) w4[tid / 64][tid % 64] = aW4[n * 192 + tid];
    if (tid < 3) b4[tid] = ab4[n * 3 + tid];
    const float* sc = scaleL + n * 64;
    const float* sh = shiftL + n * 64;
    const float* h4b = h4raw + ((size_t)n * MROWS + b * 512) * 64;
    for (int i = tid; i < 512 * 64; i += 256) {
        int l = i >> 6, k = i & 63;
        base_sh[l * 65 + k] = fmaxf(fmaf(h4b[i], sc[k], sh[k]), 0.f);
    }
    __syncthreads();
    int lane = tid & 31, warp = tid >> 5;
    const float* t3b = t3 + ((size_t)n * MROWS + b * 512) * 128;
    float* orow = out + ((size_t)b * 2048 + n * 128) * 3;
    for (int c = 0; c < 16; c++) {
        int m = warp + c * 8;
        float v[16], mx = -1e30f;
#pragma unroll
        for (int i = 0; i < 16; i++) { v[i] = t3b[(size_t)(lane + 32*i) * 128 + m]; mx = fmaxf(mx, v[i]); }
#pragma unroll
        for (int s = 16; s > 0; s >>= 1) mx = fmaxf(mx, __shfl_xor_sync(0xffffffffu, mx, s));
        float sum = 0.f;
#pragma unroll
        for (int i = 0; i < 16; i++) { v[i] = expf(v[i] - mx); sum += v[i]; }
#pragma unroll
        for (int s = 16; s > 0; s >>= 1) sum += __shfl_xor_sync(0xffffffffu, sum, s);
        float inv = 1.f / sum;
#pragma unroll
        for (int i = 0; i < 16; i++) v[i] *= inv;
        float o0 = 0.f, o1 = 0.f, o2 = 0.f;
        for (int k = 0; k < 64; k++) {
            float p = 0.f;
#pragma unroll
            for (int i = 0; i < 16; i++) p = fmaf(v[i], base_sh[(lane + 32*i) * 65 + k], p);
#pragma unroll
            for (int s = 16; s > 0; s >>= 1) p += __shfl_xor_sync(0xffffffffu, p, s);
            o0 = fmaf(w4[0][k], p, o0); o1 = fmaf(w4[1][k], p, o1); o2 = fmaf(w4[2][k], p, o2);
        }
        if (lane == 0) { orow[m*3] = o0 + b4[0]; orow[m*3+1] = o1 + b4[1]; orow[m*3+2] = o2 + b4[2]; }
    }
}

// ------------------------------- launch ------------------------------------
extern "C" void kernel_launch(void* const* d_in, const int* in_sizes, int n_in,
                              void* d_out, int out_size)
{
    (void)in_sizes; (void)n_in; (void)out_size;
    const float* x     = (const float*)d_in[0];
    const float* xpart = (const float*)d_in[1];
    const float* mW1 = (const float*)d_in[2];
    const float* mg1 = (const float*)d_in[4];
    const float* mB1 = (const float*)d_in[5];
    const float* mW2 = (const float*)d_in[6];
    const float* mg2 = (const float*)d_in[8];
    const float* mB2 = (const float*)d_in[9];
    const float* mW3 = (const float*)d_in[10];
    const float* mg3 = (const float*)d_in[12];
    const float* mB3 = (const float*)d_in[13];
    const float* mW4 = (const float*)d_in[14];
    const float* mg4 = (const float*)d_in[16];
    const float* mB4 = (const float*)d_in[17];
    const float* aW1 = (const float*)d_in[18];
    const float* ag1 = (const float*)d_in[20];
    const float* aB1 = (const float*)d_in[21];
    const float* aW2 = (const float*)d_in[22];
    const float* ag2 = (const float*)d_in[24];
    const float* aB2 = (const float*)d_in[25];
    const float* aW3 = (const float*)d_in[26];
    const float* aW4 = (const float*)d_in[28];
    const float* ab4 = (const float*)d_in[29];
    float* out = (float*)d_out;

    float *bufA, *bufB, *h4, *t1, *t2, *t3, *psum, *psq, *sc, *sh;
    __nv_bfloat16 *Ahp, *Alp, *Xh, *Xl, *W1h, *W1l, *W2h, *W2l, *W3h, *W3l, *W4h, *W4l;
    cudaGetSymbolAddress((void**)&bufA, g_bufA);
    cudaGetSymbolAddress((void**)&bufB, g_bufB);
    cudaGetSymbolAddress((void**)&h4, g_h4);
    cudaGetSymbolAddress((void**)&t1, g_t1);
    cudaGetSymbolAddress((void**)&t2, g_t2);
    cudaGetSymbolAddress((void**)&t3, g_t3);
    cudaGetSymbolAddress((void**)&psum, g_psum);
    cudaGetSymbolAddress((void**)&psq, g_psq);
    cudaGetSymbolAddress((void**)&sc, g_scale);
    cudaGetSymbolAddress((void**)&sh, g_shift);
    cudaGetSymbolAddress((void**)&Ahp, g_Ah);
    cudaGetSymbolAddress((void**)&Alp, g_Al);
    cudaGetSymbolAddress((void**)&Xh, g_Xh);
    cudaGetSymbolAddress((void**)&Xl, g_Xl);
    cudaGetSymbolAddress((void**)&W1h, g_W1h);
    cudaGetSymbolAddress((void**)&W1l, g_W1l);
    cudaGetSymbolAddress((void**)&W2h, g_W2h);
    cudaGetSymbolAddress((void**)&W2l, g_W2l);
    cudaGetSymbolAddress((void**)&W3h, g_W3h);
    cudaGetSymbolAddress((void**)&W3l, g_W3l);
    cudaGetSymbolAddress((void**)&W4h, g_W4h);
    cudaGetSymbolAddress((void**)&W4l, g_W4l);

    static bool init_done = false;
    static cudaStream_t s2;
    static cudaEvent_t evFork, evJoin;
    if (!init_done) {
        cudaFuncSetAttribute(softmax_pts_kernel, cudaFuncAttributeMaxDynamicSharedMemorySize, 512 * 65 * 4);
        cudaFuncSetAttribute(gemm_mma2, cudaFuncAttributeMaxDynamicSharedMemorySize, 81920);
        cudaStreamCreateWithFlags(&s2, cudaStreamNonBlocking);
        cudaEventCreateWithFlags(&evFork, cudaEventDisableTiming);
        cudaEventCreateWithFlags(&evJoin, cudaEventDisableTiming);
        init_done = true;
    }

    const int SL = NBR * 512;
    const long MS512 = (long)MROWS * 512;
    const long MS64  = (long)MROWS * 64;
    const long MS128 = (long)MROWS * 128;

    // fork: FPS on side stream (writes out rows [1024,2048) only)
    cudaEventRecord(evFork, 0);
    cudaStreamWaitEvent(s2, evFork, 0);
    fps_kernel<<<32 * FPS_CL, 512, 0, s2>>>(xpart, out);
    cudaEventRecord(evJoin, s2);

    conv_plain<<<(NBR*512*128)/256, 256>>>(mW1, W1h, W1l, NBR*512*128);
    conv_plain<<<(NBR*512*256)/256, 256>>>(mW2, W2h, W2l, NBR*512*256);
    conv_plain<<<(NBR*512*256)/256, 256>>>(mW3, W3h, W3l, NBR*512*256);
    conv_w4<<<(NBR*128*256)/256, 256>>>(mW4, W4h, W4l);
    conv_plain<<<(MROWS*128)/256, 256>>>(x, Xh, Xl, MROWS*128);

    gemm_mma2<<<dim3(4, 128, NBR), 256, 81920>>>(Xh, Xl, W1h, W1l, bufA, psum, psq,
                                                 256, 0, 512L*256, 512);
    bn_finalize<<<16, 256>>>(psum, psq, mg1, mB1, sc, sh, NBR * 512);

    conv_bn<<<NBR * MROWS, 256>>>(bufA, sc, sh, Ahp, Alp);
    gemm_mma2<<<dim3(4, 128, NBR), 256, 81920>>>(Ahp, Alp, W2h, W2l, bufB, psum, psq,
                                                 512, MS512, 512L*512, 512);
    bn_finalize<<<16, 256>>>(psum, psq, mg2, mB2, sc + SL, sh + SL, NBR * 512);

    conv_bn<<<NBR * MROWS, 256>>>(bufB, sc + SL, sh + SL, Ahp, Alp);
    gemm_mma2<<<dim3(4, 128, NBR), 256, 81920>>>(Ahp, Alp, W3h, W3l, bufA, psum, psq,
                                                 512, MS512, 512L*512, 512);
    bn_finalize<<<16, 256>>>(psum, psq, mg3, mB3, sc + 2 * SL, sh + 2 * SL, NBR * 512);

    // L4 on tensor cores: conv_bn(L3 raw) then 128-padded-N GEMM -> h4 [M,64]
    conv_bn<<<NBR * MROWS, 256>>>(bufA, sc + 2 * SL, sh + 2 * SL, Ahp, Alp);
    gemm_mma2<<<dim3(1, 128, NBR), 256, 81920>>>(Ahp, Alp, W4h, W4l, h4, psum, psq,
                                                 512, MS512, 128L*512, 64);
    bn_finalize<<<2, 256>>>(psum, psq, mg4, mB4, sc + 3 * SL, sh + 3 * SL, NBR * 64);

    gemm_bn<64, 4, true, true><<<dim3(1, 128, NBR), 256>>>(
        h4, aW1, t1, sc + 3 * SL, sh + 3 * SL, psum, psq, MROWS, 64, 64, MS64);
    bn_finalize<<<2, 256>>>(psum, psq, ag1, aB1, sc + 4 * SL, sh + 4 * SL, NBR * 64);

    gemm_bn<128, 8, true, true><<<dim3(1, 128, NBR), 256>>>(
        t1, aW2, t2, sc + 4 * SL, sh + 4 * SL, psum, psq, MROWS, 128, 64, MS64);
    bn_finalize<<<4, 256>>>(psum, psq, ag2, aB2, sc + 5 * SL, sh + 5 * SL, NBR * 128);

    gemm_bn<128, 8, true, false><<<dim3(1, 128, NBR), 256>>>(
        t2, aW3, t3, sc + 5 * SL, sh + 5 * SL, nullptr, nullptr, MROWS, 128, 128, MS128);

    softmax_pts_kernel<<<dim3(32, NBR), 256, 512 * 65 * 4>>>(
        t3, h4, sc + 3 * SL, sh + 3 * SL, aW4, ab4, out);

    // join FPS before returning
    cudaStreamWaitEvent(0, evJoin, 0);
}

// round 8
// speedup vs baseline: 2.7082x; 1.0788x over previous
#include <cuda_runtime.h>
#include <cuda_bf16.h>
#include <cstdint>
#include <cstddef>

#define NBR 8
#define MROWS 16384
#define BN_EPS 1e-5f

__device__ __align__(256) float g_bufA[(size_t)NBR * MROWS * 512];
__device__ __align__(256) float g_bufB[(size_t)NBR * MROWS * 512];
__device__ __align__(256) float g_h4 [(size_t)NBR * MROWS * 64];
__device__ __align__(256) float g_t1 [(size_t)NBR * MROWS * 64];
__device__ __align__(256) float g_t2 [(size_t)NBR * MROWS * 128];
__device__ __align__(256) float g_t3 [(size_t)NBR * MROWS * 128];
__device__ float g_psum [NBR * 512 * 128];
__device__ float g_psq  [NBR * 512 * 128];
__device__ float g_scale[6 * NBR * 512];
__device__ float g_shift[6 * NBR * 512];
__device__ __align__(16) __nv_bfloat16 g_Ah[(size_t)NBR * MROWS * 512];
__device__ __align__(16) __nv_bfloat16 g_Al[(size_t)NBR * MROWS * 512];
__device__ __align__(16) __nv_bfloat16 g_Xh[(size_t)MROWS * 256];
__device__ __align__(16) __nv_bfloat16 g_Xl[(size_t)MROWS * 256];
__device__ __align__(16) __nv_bfloat16 g_W1h[NBR * 512 * 256];
__device__ __align__(16) __nv_bfloat16 g_W1l[NBR * 512 * 256];
__device__ __align__(16) __nv_bfloat16 g_W2h[NBR * 512 * 512];
__device__ __align__(16) __nv_bfloat16 g_W2l[NBR * 512 * 512];
__device__ __align__(16) __nv_bfloat16 g_W3h[NBR * 512 * 512];
__device__ __align__(16) __nv_bfloat16 g_W3l[NBR * 512 * 512];
__device__ __align__(16) __nv_bfloat16 g_W4h[NBR * 128 * 512];
__device__ __align__(16) __nv_bfloat16 g_W4l[NBR * 128 * 512];

__device__ __forceinline__ uint32_t smem_u32(const void* p) {
    uint32_t a;
    asm("{ .reg .u64 t; cvta.to.shared.u64 t, %1; cvt.u32.u64 %0, t; }" : "=r"(a) : "l"(p));
    return a;
}
__device__ __forceinline__ void stc_f32(uint32_t sa, uint32_t rank, float v) {
    uint32_t r;
    asm volatile("mapa.shared::cluster.u32 %0, %1, %2;" : "=r"(r) : "r"(sa), "r"(rank));
    asm volatile("st.shared::cluster.f32 [%0], %1;" :: "r"(r), "f"(v) : "memory");
}
__device__ __forceinline__ void stc_u32(uint32_t sa, uint32_t rank, uint32_t v) {
    uint32_t r;
    asm volatile("mapa.shared::cluster.u32 %0, %1, %2;" : "=r"(r) : "r"(sa), "r"(rank));
    asm volatile("st.shared::cluster.u32 [%0], %1;" :: "r"(r), "r"(v) : "memory");
}
__device__ __forceinline__ void cpa16(uint32_t d, const void* g) {
    asm volatile("cp.async.cg.shared.global [%0], [%1], 16;" :: "r"(d), "l"(g));
}
#define CP_COMMIT() asm volatile("cp.async.commit_group;")
#define CP_WAIT(N)  asm volatile("cp.async.wait_group %0;" :: "n"(N))
#define LDSM4(R, ADDR) \
    asm volatile("ldmatrix.sync.aligned.m8n8.x4.shared.b16 {%0,%1,%2,%3}, [%4];" \
        : "=r"((R)[0]), "=r"((R)[1]), "=r"((R)[2]), "=r"((R)[3]) : "r"(ADDR))
#define MMA16816(D, A, B0, B1) \
    asm volatile("mma.sync.aligned.m16n8k16.row.col.f32.bf16.bf16.f32 " \
        "{%0,%1,%2,%3}, {%4,%5,%6,%7}, {%8,%9}, {%0,%1,%2,%3};" \
        : "+f"((D)[0]), "+f"((D)[1]), "+f"((D)[2]), "+f"((D)[3]) \
        : "r"((A)[0]), "r"((A)[1]), "r"((A)[2]), "r"((A)[3]), "r"(B0), "r"(B1))

// ------------------------------ FPS (proven) --------------------------------
#define FPS_CL 4
__global__ void __cluster_dims__(FPS_CL,1,1) __launch_bounds__(512,1)
fps_kernel(const float* __restrict__ xpart, float* __restrict__ out)
{
    uint32_t rank; asm("mov.u32 %0, %%cluster_ctarank;" : "=r"(rank));
    int b = blockIdx.x / FPS_CL;
    const float* xp = xpart + (size_t)b * 32768 * 3;
    int tid = threadIdx.x, lane = tid & 31, warp = tid >> 5;
    int pbase = (int)rank * 8192;
    float px[16], py[16], pz[16], dd[16];
#pragma unroll
    for (int i = 0; i < 16; i++) {
        int p = pbase + tid + 512 * i;
        px[i] = xp[p*3]; py[i] = xp[p*3+1]; pz[i] = xp[p*3+2]; dd[i] = 1e10f;
    }
    __shared__ float wv_[16]; __shared__ int wi_[16];
    __shared__ float wx_[16], wy_[16], wz_[16];
    __shared__ float cval[2][FPS_CL]; __shared__ int cidx[2][FPS_CL];
    __shared__ float cxx[2][FPS_CL], cyy[2][FPS_CL], czz[2][FPS_CL];
    float curx = xp[0], cury = xp[1], curz = xp[2];
    float* orow = out + ((size_t)b * 2048 + 1024) * 3;
    if (rank == 0 && tid == 0) { orow[0]=curx; orow[1]=cury; orow[2]=curz; }

    for (int t = 1; t < 1024; t++) {
        float bv = -1.f; int bi = 0x7fffffff;
        float bx = 0.f, by = 0.f, bz = 0.f;
#pragma unroll
        for (int i = 0; i < 16; i++) {
            float dx = __fsub_rn(px[i], curx), dy = __fsub_rn(py[i], cury), dz = __fsub_rn(pz[i], curz);
            float d = __fadd_rn(__fadd_rn(__fmul_rn(dx,dx), __fmul_rn(dy,dy)), __fmul_rn(dz,dz));
            dd[i] = fminf(dd[i], d);
            int gi = pbase + tid + 512 * i;
            if (dd[i] > bv || (dd[i] == bv && gi < bi)) { bv=dd[i]; bi=gi; bx=px[i]; by=py[i]; bz=pz[i]; }
        }
#pragma unroll
        for (int s = 16; s > 0; s >>= 1) {
            float ov = __shfl_down_sync(0xffffffffu, bv, s);
            int   oi = __shfl_down_sync(0xffffffffu, bi, s);
            float ox = __shfl_down_sync(0xffffffffu, bx, s);
            float oy = __shfl_down_sync(0xffffffffu, by, s);
            float oz = __shfl_down_sync(0xffffffffu, bz, s);
            if (ov > bv || (ov == bv && oi < bi)) { bv=ov; bi=oi; bx=ox; by=oy; bz=oz; }
        }
        if (lane == 0) { wv_[warp]=bv; wi_[warp]=bi; wx_[warp]=bx; wy_[warp]=by; wz_[warp]=bz; }
        __syncthreads();
        int par = t & 1;
        if (warp == 0) {
            bv = (lane < 16) ? wv_[lane] : -1.f;
            bi = (lane < 16) ? wi_[lane] : 0x7fffffff;
            bx = (lane < 16) ? wx_[lane] : 0.f;
            by = (lane < 16) ? wy_[lane] : 0.f;
            bz = (lane < 16) ? wz_[lane] : 0.f;
#pragma unroll
            for (int s = 8; s > 0; s >>= 1) {
                float ov = __shfl_down_sync(0xffffffffu, bv, s);
                int   oi = __shfl_down_sync(0xffffffffu, bi, s);
                float ox = __shfl_down_sync(0xffffffffu, bx, s);
                float oy = __shfl_down_sync(0xffffffffu, by, s);
                float oz = __shfl_down_sync(0xffffffffu, bz, s);
                if (ov > bv || (ov == bv && oi < bi)) { bv=ov; bi=oi; bx=ox; by=oy; bz=oz; }
            }
            if (lane == 0) {
                for (uint32_t r = 0; r < FPS_CL; r++) {
                    stc_f32(smem_u32(&cval[par][rank]), r, bv);
                    stc_u32(smem_u32(&cidx[par][rank]), r, (uint32_t)bi);
                    stc_f32(smem_u32(&cxx[par][rank]), r, bx);
                    stc_f32(smem_u32(&cyy[par][rank]), r, by);
                    stc_f32(smem_u32(&czz[par][rank]), r, bz);
                }
            }
        }
        asm volatile("barrier.cluster.arrive.aligned;" ::: "memory");
        asm volatile("barrier.cluster.wait.aligned;" ::: "memory");
        float vv = cval[par][0]; int vi = cidx[par][0];
        float nx = cxx[par][0], ny = cyy[par][0], nz = czz[par][0];
#pragma unroll
        for (int r = 1; r < FPS_CL; r++) {
            float ov = cval[par][r]; int oi = cidx[par][r];
            if (ov > vv || (ov == vv && oi < vi)) { vv=ov; vi=oi; nx=cxx[par][r]; ny=cyy[par][r]; nz=czz[par][r]; }
        }
        curx = nx; cury = ny; curz = nz;
        if (rank == 0 && tid == 0) { orow[t*3]=nx; orow[t*3+1]=ny; orow[t*3+2]=nz; }
    }
}

// ------------------------- conversion passes -------------------------------
__global__ void conv_plain(const float* __restrict__ S, __nv_bfloat16* __restrict__ H,
                           __nv_bfloat16* __restrict__ L, int nPairs)
{
    int p = blockIdx.x * 256 + threadIdx.x;
    if (p >= nPairs) return;
    float2 v = *(const float2*)(S + (size_t)p * 2);
    __nv_bfloat162 hp, lp;
    hp.x = __float2bfloat16(v.x); hp.y = __float2bfloat16(v.y);
    lp.x = __float2bfloat16(v.x - __bfloat162float(hp.x));
    lp.y = __float2bfloat16(v.y - __bfloat162float(hp.y));
    *(__nv_bfloat162*)(H + (size_t)p * 2) = hp;
    *(__nv_bfloat162*)(L + (size_t)p * 2) = lp;
}
__global__ void conv_w4(const float* __restrict__ S, __nv_bfloat16* __restrict__ H,
                        __nv_bfloat16* __restrict__ L)
{
    int p = blockIdx.x * 256 + threadIdx.x;
    if (p >= NBR * 128 * 256) return;
    int k2 = p & 255, rem = p >> 8, n = rem & 127, z = rem >> 7;
    __nv_bfloat162 hp, lp;
    if (n < 64) {
        float2 v = *(const float2*)(S + (((size_t)z * 64 + n) * 512) + k2 * 2);
        hp.x = __float2bfloat16(v.x); hp.y = __float2bfloat16(v.y);
        lp.x = __float2bfloat16(v.x - __bfloat162float(hp.x));
        lp.y = __float2bfloat16(v.y - __bfloat162float(hp.y));
    } else {
        hp.x = hp.y = lp.x = lp.y = __float2bfloat16(0.f);
    }
    *(__nv_bfloat162*)(H + (size_t)p * 2) = hp;
    *(__nv_bfloat162*)(L + (size_t)p * 2) = lp;
}
__global__ void conv_bn(const float* __restrict__ raw, const float* __restrict__ sc,
                        const float* __restrict__ sh, __nv_bfloat16* __restrict__ H,
                        __nv_bfloat16* __restrict__ L)
{
    int p = blockIdx.x * 256 + threadIdx.x;
    int k = (p & 255) * 2, row = p >> 8, z = row >> 14;
    float2 v = *(const float2*)(raw + (size_t)row * 512 + k);
    float a0 = fmaxf(fmaf(v.x, sc[z*512+k],   sh[z*512+k]),   0.f);
    float a1 = fmaxf(fmaf(v.y, sc[z*512+k+1], sh[z*512+k+1]), 0.f);
    __nv_bfloat162 hp, lp;
    hp.x = __float2bfloat16(a0); hp.y = __float2bfloat16(a1);
    lp.x = __float2bfloat16(a0 - __bfloat162float(hp.x));
    lp.y = __float2bfloat16(a1 - __bfloat162float(hp.y));
    *(__nv_bfloat162*)(H + (size_t)row * 512 + k) = hp;
    *(__nv_bfloat162*)(L + (size_t)row * 512 + k) = lp;
}

// -------------- bf16-split tensor-core GEMM, cp.async, 2 CTAs/SM ----------
__global__ void __launch_bounds__(256, 2)
gemm_mma2(const __nv_bfloat16* __restrict__ Agh, const __nv_bfloat16* __restrict__ Agl,
          const __nv_bfloat16* __restrict__ Bgh, const __nv_bfloat16* __restrict__ Bgl,
          float* __restrict__ Call, float* __restrict__ psum, float* __restrict__ psq,
          int K, long aStride, long bStride, int Nout)
{
    extern __shared__ __align__(16) uint32_t sm[];
    int bx = blockIdx.x, by = blockIdx.y, z = blockIdx.z;
    int tid = threadIdx.x, lane = tid & 31, w = tid >> 5;
    int wm = w & 1, wn = w >> 1;
    int m0 = by * 128, n0 = bx * 128, KC = K >> 5;
    const __nv_bfloat16* Ah = Agh + (size_t)z * aStride;
    const __nv_bfloat16* Al = Agl + (size_t)z * aStride;
    const __nv_bfloat16* Bh = Bgh + (size_t)z * bStride;
    const __nv_bfloat16* Bl = Bgl + (size_t)z * bStride;
    uint32_t sbase = smem_u32(sm);

    int lr = tid >> 1, half = tid & 1;
    const __nv_bfloat16* Ar_h = Ah + (size_t)(m0 + lr) * K + half * 16;
    const __nv_bfloat16* Ar_l = Al + (size_t)(m0 + lr) * K + half * 16;
    const __nv_bfloat16* Br_h = Bh + (size_t)(n0 + lr) * K + half * 16;
    const __nv_bfloat16* Br_l = Bl + (size_t)(n0 + lr) * K + half * 16;
    uint32_t drow = lr * 80 + half * 32;

    auto fill = [&](int kc, int s) {
        uint32_t st = sbase + s * 40960;
        int go = kc * 32;
        cpa16(st + drow,                Ar_h + go);
        cpa16(st + drow + 16,           Ar_h + go + 8);
        cpa16(st + 10240 + drow,        Ar_l + go);
        cpa16(st + 10240 + drow + 16,   Ar_l + go + 8);
        cpa16(st + 20480 + drow,        Br_h + go);
        cpa16(st + 20480 + drow + 16,   Br_h + go + 8);
        cpa16(st + 30720 + drow,        Br_l + go);
        cpa16(st + 30720 + drow + 16,   Br_l + go + 8);
    };

    float acc[4][4][4];
#pragma unroll
    for (int i = 0; i < 4; i++)
#pragma unroll
        for (int j = 0; j < 4; j++)
#pragma unroll
            for (int e = 0; e < 4; e++) acc[i][j][e] = 0.f;

    fill(0, 0); CP_COMMIT();
    fill(1, 1); CP_COMMIT();

    int arow = lane & 15, kh = (lane >> 4) * 8;
    int bn_ = ((lane >> 4) & 1) * 8 + (lane & 7), bk = ((lane >> 3) & 1) * 8;

    for (int kc = 0; kc < KC; kc++) {
        int s = kc & 1;
        if (kc + 1 < KC) { CP_WAIT(1); } else { CP_WAIT(0); }
        __syncthreads();
        uint32_t abase = sbase + s * 40960 + (wm * 64) * 80;
        uint32_t bbase = sbase + s * 40960 + 20480 + (wn * 32) * 80;
#pragma unroll
        for (int ks = 0; ks < 2; ks++) {
            // B fragments once per ks (low register pressure)
            uint32_t bh[2][4], blr[2][4];
#pragma unroll
            for (int g = 0; g < 2; g++) {
                uint32_t bd = bbase + (g*16 + bn_) * 80 + (ks*16 + bk) * 2;
                LDSM4(bh[g], bd);
                LDSM4(blr[g], bd + 10240);
            }
            // A fragments per mt (keeps live regs low for 2 CTAs/SM)
#pragma unroll
            for (int mt = 0; mt < 4; mt++) {
                uint32_t ah[4], alr[4];
                uint32_t ad = abase + (mt*16 + arow) * 80 + (ks*16 + kh) * 2;
                LDSM4(ah, ad);
                LDSM4(alr, ad + 10240);
#pragma unroll
                for (int nt = 0; nt < 4; nt++) {
                    int g = nt >> 1, p = (nt & 1) * 2;
                    MMA16816(acc[mt][nt], ah,  bh[g][p],  bh[g][p+1]);
                    MMA16816(acc[mt][nt], ah,  blr[g][p], blr[g][p+1]);
                    MMA16816(acc[mt][nt], alr, bh[g][p],  bh[g][p+1]);
                }
            }
        }
        __syncthreads();
        if (kc + 2 < KC) { fill(kc + 2, s); CP_COMMIT(); }
    }

    // epilogue
    float* cs = (float*)sm;
#pragma unroll
    for (int mt = 0; mt < 4; mt++)
#pragma unroll
        for (int nt = 0; nt < 4; nt++) {
            int r = wm*64 + mt*16 + (lane >> 2);
            int c = wn*32 + nt*8 + (lane & 3) * 2;
            *(float2*)(cs + r*132 + c)     = make_float2(acc[mt][nt][0], acc[mt][nt][1]);
            *(float2*)(cs + (r+8)*132 + c) = make_float2(acc[mt][nt][2], acc[mt][nt][3]);
        }
    __syncthreads();
    if (tid < 128 && n0 + tid < Nout) {
        float s = 0.f, q = 0.f;
#pragma unroll 8
        for (int r = 0; r < 128; r++) { float v = cs[r*132 + tid]; s += v; q = fmaf(v, v, q); }
        size_t ch = (size_t)z * Nout + n0 + tid;
        psum[ch * 128 + by] = s; psq[ch * 128 + by] = q;
    }
    float* C = Call + (size_t)z * MROWS * Nout;
#pragma unroll
    for (int i = 0; i < 16; i++) {
        int lin = tid + 256 * i;
        int r = lin >> 5, c4 = (lin & 31) * 4;
        if (n0 + c4 < Nout) {
            float4 v = *(float4*)(cs + r*132 + c4);
            *(float4*)(C + (size_t)(m0 + r) * Nout + n0 + c4) = v;
        }
    }
}

// --------------------------- SIMT small GEMM (proven) -----------------------
template<int BN, int TN, bool HAS_T, bool HAS_S>
__global__ void __launch_bounds__(256)
gemm_bn(const float* __restrict__ Aall, const float* __restrict__ Wall, float* __restrict__ Call,
        const float* __restrict__ tsc, const float* __restrict__ tsh,
        float* __restrict__ psum, float* __restrict__ psq, int M, int N, int K, long aStride)
{
    constexpr int BM = 128, BK = 8, TM = 8;
    int z = blockIdx.z;
    const float* A = Aall + (size_t)z * (size_t)aStride;
    const float* W = Wall + (size_t)z * N * K;
    float* C = Call + (size_t)z * (size_t)M * N;
    const float* sc = HAS_T ? (tsc + z * K) : nullptr;
    const float* sh = HAS_T ? (tsh + z * K) : nullptr;
    __shared__ float As[BK][BM], Bs[BK][BN], red[16][BN];
    int t = threadIdx.x, m0 = blockIdx.y * BM, n0 = blockIdx.x * BN;
    int tcol = t & 15, trow = t >> 4;
    float acc[TM][TN];
#pragma unroll
    for (int i = 0; i < TM; i++)
#pragma unroll
        for (int j = 0; j < TN; j++) acc[i][j] = 0.f;
    int ar = t >> 1, ac4 = (t & 1) * 4;
    const float* Aload = A + (size_t)(m0 + ar) * K + ac4;
    for (int k0 = 0; k0 < K; k0 += BK) {
        float4 avv = *(const float4*)(Aload + k0);
        if (HAS_T) {
            int c = k0 + ac4;
            avv.x = fmaxf(fmaf(avv.x, sc[c],   sh[c]),   0.f);
            avv.y = fmaxf(fmaf(avv.y, sc[c+1], sh[c+1]), 0.f);
            avv.z = fmaxf(fmaf(avv.z, sc[c+2], sh[c+2]), 0.f);
            avv.w = fmaxf(fmaf(avv.w, sc[c+3], sh[c+3]), 0.f);
        }
        As[ac4][ar] = avv.x; As[ac4+1][ar] = avv.y; As[ac4+2][ar] = avv.z; As[ac4+3][ar] = avv.w;
        for (int e = t; e < BN * 2; e += 256) {
            int wr = e >> 1, wc = (e & 1) * 4;
            float4 wv = *(const float4*)(W + (size_t)(n0 + wr) * K + k0 + wc);
            Bs[wc][wr] = wv.x; Bs[wc+1][wr] = wv.y; Bs[wc+2][wr] = wv.z; Bs[wc+3][wr] = wv.w;
        }
        __syncthreads();
#pragma unroll
        for (int kk = 0; kk < BK; kk++) {
            float a[TM], bb[TN];
            const float4* A4 = (const float4*)(&As[kk][trow * TM]);
            float4 t0 = A4[0], t1 = A4[1];
            a[0]=t0.x; a[1]=t0.y; a[2]=t0.z; a[3]=t0.w; a[4]=t1.x; a[5]=t1.y; a[6]=t1.z; a[7]=t1.w;
            const float4* B4 = (const float4*)(&Bs[kk][tcol * TN]);
            float4 u0 = B4[0];
            bb[0]=u0.x; bb[1]=u0.y; bb[2]=u0.z; bb[3]=u0.w;
            if constexpr (TN == 8) { float4 u1 = B4[1]; bb[4]=u1.x; bb[5]=u1.y; bb[6]=u1.z; bb[7]=u1.w; }
#pragma unroll
            for (int i = 0; i < TM; i++)
#pragma unroll
                for (int j = 0; j < TN; j++) acc[i][j] = fmaf(a[i], bb[j], acc[i][j]);
        }
        __syncthreads();
    }
#pragma unroll
    for (int i = 0; i < TM; i++) {
        float* crow = C + (size_t)(m0 + trow * TM + i) * N + n0 + tcol * TN;
#pragma unroll
        for (int j = 0; j < TN; j += 4)
            *(float4*)(crow + j) = make_float4(acc[i][j], acc[i][j+1], acc[i][j+2], acc[i][j+3]);
    }
    if (HAS_S) {
        float cs2[TN], cq[TN];
#pragma unroll
        for (int j = 0; j < TN; j++) {
            cs2[j] = 0.f; cq[j] = 0.f;
#pragma unroll
            for (int i = 0; i < TM; i++) { cs2[j] += acc[i][j]; cq[j] = fmaf(acc[i][j], acc[i][j], cq[j]); }
        }
#pragma unroll
        for (int j = 0; j < TN; j++) red[trow][tcol * TN + j] = cs2[j];
        __syncthreads();
        for (int s = 8; s > 0; s >>= 1) {
            if (trow < s)
#pragma unroll
                for (int j = 0; j < TN; j++) red[trow][tcol*TN+j] += red[trow+s][tcol*TN+j];
            __syncthreads();
        }
        if (trow == 0)
#pragma unroll
            for (int j = 0; j < TN; j++)
                psum[(size_t)(z * N + n0 + tcol * TN + j) * 128 + blockIdx.y] = red[0][tcol*TN+j];
        __syncthreads();
#pragma unroll
        for (int j = 0; j < TN; j++) red[trow][tcol * TN + j] = cq[j];
        __syncthreads();
        for (int s = 8; s > 0; s >>= 1) {
            if (trow < s)
#pragma unroll
                for (int j = 0; j < TN; j++) red[trow][tcol*TN+j] += red[trow+s][tcol*TN+j];
            __syncthreads();
        }
        if (trow == 0)
#pragma unroll
            for (int j = 0; j < TN; j++)
                psq[(size_t)(z * N + n0 + tcol * TN + j) * 128 + blockIdx.y] = red[0][tcol*TN+j];
    }
}

__global__ void bn_finalize(const float* __restrict__ psum, const float* __restrict__ psq,
                            const float* __restrict__ gam, const float* __restrict__ bet,
                            float* __restrict__ sc, float* __restrict__ sh, int total)
{
    int i = blockIdx.x * blockDim.x + threadIdx.x;
    if (i >= total) return;
    float s = 0.f, q = 0.f;
    const float* ps = psum + (size_t)i * 128;
    const float* pq = psq + (size_t)i * 128;
#pragma unroll 8
    for (int k = 0; k < 128; k++) { s += ps[k]; q += pq[k]; }
    float mean = s * (1.f / 16384.f);
    float var = fmaf(-mean, mean, q * (1.f / 16384.f));
    float g = gam[i] * rsqrtf(var + BN_EPS);
    sc[i] = g; sh[i] = fmaf(-mean, g, bet[i]);
}

// ----------------------------- softmax/pool (proven) ------------------------
__global__ void __launch_bounds__(256, 1)
softmax_pts_kernel(const float* __restrict__ t3, const float* __restrict__ h4raw,
                   const float* __restrict__ scaleL, const float* __restrict__ shiftL,
                   const float* __restrict__ aW4, const float* __restrict__ ab4,
                   float* __restrict__ out)
{
    int b = blockIdx.x, n = blockIdx.y;
    extern __shared__ float base_sh[];
    __shared__ float w4[3][64], b4[3];
    int tid = threadIdx.x;
    if (tid < 192) w4[tid / 64][tid % 64] = aW4[n * 192 + tid];
    if (tid < 3) b4[tid] = ab4[n * 3 + tid];
    const float* sc = scaleL + n * 64;
    const float* sh = shiftL + n * 64;
    const float* h4b = h4raw + ((size_t)n * MROWS + b * 512) * 64;
    for (int i = tid; i < 512 * 64; i += 256) {
        int l = i >> 6, k = i & 63;
        base_sh[l * 65 + k] = fmaxf(fmaf(h4b[i], sc[k], sh[k]), 0.f);
    }
    __syncthreads();
    int lane = tid & 31, warp = tid >> 5;
    const float* t3b = t3 + ((size_t)n * MROWS + b * 512) * 128;
    float* orow = out + ((size_t)b * 2048 + n * 128) * 3;
    for (int c = 0; c < 16; c++) {
        int m = warp + c * 8;
        float v[16], mx = -1e30f;
#pragma unroll
        for (int i = 0; i < 16; i++) { v[i] = t3b[(size_t)(lane + 32*i) * 128 + m]; mx = fmaxf(mx, v[i]); }
#pragma unroll
        for (int s = 16; s > 0; s >>= 1) mx = fmaxf(mx, __shfl_xor_sync(0xffffffffu, mx, s));
        float sum = 0.f;
#pragma unroll
        for (int i = 0; i < 16; i++) { v[i] = expf(v[i] - mx); sum += v[i]; }
#pragma unroll
        for (int s = 16; s > 0; s >>= 1) sum += __shfl_xor_sync(0xffffffffu, sum, s);
        float inv = 1.f / sum;
#pragma unroll
        for (int i = 0; i < 16; i++) v[i] *= inv;
        float o0 = 0.f, o1 = 0.f, o2 = 0.f;
        for (int k = 0; k < 64; k++) {
            float p = 0.f;
#pragma unroll
            for (int i = 0; i < 16; i++) p = fmaf(v[i], base_sh[(lane + 32*i) * 65 + k], p);
#pragma unroll
            for (int s = 16; s > 0; s >>= 1) p += __shfl_xor_sync(0xffffffffu, p, s);
            o0 = fmaf(w4[0][k], p, o0); o1 = fmaf(w4[1][k], p, o1); o2 = fmaf(w4[2][k], p, o2);
        }
        if (lane == 0) { orow[m*3] = o0 + b4[0]; orow[m*3+1] = o1 + b4[1]; orow[m*3+2] = o2 + b4[2]; }
    }
}

// ------------------------------- launch ------------------------------------
extern "C" void kernel_launch(void* const* d_in, const int* in_sizes, int n_in,
                              void* d_out, int out_size)
{
    (void)in_sizes; (void)n_in; (void)out_size;
    const float* x     = (const float*)d_in[0];
    const float* xpart = (const float*)d_in[1];
    const float* mW1 = (const float*)d_in[2];
    const float* mg1 = (const float*)d_in[4];
    const float* mB1 = (const float*)d_in[5];
    const float* mW2 = (const float*)d_in[6];
    const float* mg2 = (const float*)d_in[8];
    const float* mB2 = (const float*)d_in[9];
    const float* mW3 = (const float*)d_in[10];
    const float* mg3 = (const float*)d_in[12];
    const float* mB3 = (const float*)d_in[13];
    const float* mW4 = (const float*)d_in[14];
    const float* mg4 = (const float*)d_in[16];
    const float* mB4 = (const float*)d_in[17];
    const float* aW1 = (const float*)d_in[18];
    const float* ag1 = (const float*)d_in[20];
    const float* aB1 = (const float*)d_in[21];
    const float* aW2 = (const float*)d_in[22];
    const float* ag2 = (const float*)d_in[24];
    const float* aB2 = (const float*)d_in[25];
    const float* aW3 = (const float*)d_in[26];
    const float* aW4 = (const float*)d_in[28];
    const float* ab4 = (const float*)d_in[29];
    float* out = (float*)d_out;

    float *bufA, *bufB, *h4, *t1, *t2, *t3, *psum, *psq, *sc, *sh;
    __nv_bfloat16 *Ahp, *Alp, *Xh, *Xl, *W1h, *W1l, *W2h, *W2l, *W3h, *W3l, *W4h, *W4l;
    cudaGetSymbolAddress((void**)&bufA, g_bufA);
    cudaGetSymbolAddress((void**)&bufB, g_bufB);
    cudaGetSymbolAddress((void**)&h4, g_h4);
    cudaGetSymbolAddress((void**)&t1, g_t1);
    cudaGetSymbolAddress((void**)&t2, g_t2);
    cudaGetSymbolAddress((void**)&t3, g_t3);
    cudaGetSymbolAddress((void**)&psum, g_psum);
    cudaGetSymbolAddress((void**)&psq, g_psq);
    cudaGetSymbolAddress((void**)&sc, g_scale);
    cudaGetSymbolAddress((void**)&sh, g_shift);
    cudaGetSymbolAddress((void**)&Ahp, g_Ah);
    cudaGetSymbolAddress((void**)&Alp, g_Al);
    cudaGetSymbolAddress((void**)&Xh, g_Xh);
    cudaGetSymbolAddress((void**)&Xl, g_Xl);
    cudaGetSymbolAddress((void**)&W1h, g_W1h);
    cudaGetSymbolAddress((void**)&W1l, g_W1l);
    cudaGetSymbolAddress((void**)&W2h, g_W2h);
    cudaGetSymbolAddress((void**)&W2l, g_W2l);
    cudaGetSymbolAddress((void**)&W3h, g_W3h);
    cudaGetSymbolAddress((void**)&W3l, g_W3l);
    cudaGetSymbolAddress((void**)&W4h, g_W4h);
    cudaGetSymbolAddress((void**)&W4l, g_W4l);

    static bool init_done = false;
    static cudaStream_t s2;
    static cudaEvent_t evFork, evJoin;
    if (!init_done) {
        cudaFuncSetAttribute(softmax_pts_kernel, cudaFuncAttributeMaxDynamicSharedMemorySize, 512 * 65 * 4);
        cudaFuncSetAttribute(gemm_mma2, cudaFuncAttributeMaxDynamicSharedMemorySize, 81920);
        cudaStreamCreateWithFlags(&s2, cudaStreamNonBlocking);
        cudaEventCreateWithFlags(&evFork, cudaEventDisableTiming);
        cudaEventCreateWithFlags(&evJoin, cudaEventDisableTiming);
        init_done = true;
    }

    const int SL = NBR * 512;
    const long MS512 = (long)MROWS * 512;
    const long MS64  = (long)MROWS * 64;
    const long MS128 = (long)MROWS * 128;

    cudaEventRecord(evFork, 0);
    cudaStreamWaitEvent(s2, evFork, 0);
    fps_kernel<<<32 * FPS_CL, 512, 0, s2>>>(xpart, out);
    cudaEventRecord(evJoin, s2);

    conv_plain<<<(NBR*512*128)/256, 256>>>(mW1, W1h, W1l, NBR*512*128);
    conv_plain<<<(NBR*512*256)/256, 256>>>(mW2, W2h, W2l, NBR*512*256);
    conv_plain<<<(NBR*512*256)/256, 256>>>(mW3, W3h, W3l, NBR*512*256);
    conv_w4<<<(NBR*128*256)/256, 256>>>(mW4, W4h, W4l);
    conv_plain<<<(MROWS*128)/256, 256>>>(x, Xh, Xl, MROWS*128);

    gemm_mma2<<<dim3(4, 128, NBR), 256, 81920>>>(Xh, Xl, W1h, W1l, bufA, psum, psq,
                                                 256, 0, 512L*256, 512);
    bn_finalize<<<16, 256>>>(psum, psq, mg1, mB1, sc, sh, NBR * 512);

    conv_bn<<<NBR * MROWS, 256>>>(bufA, sc, sh, Ahp, Alp);
    gemm_mma2<<<dim3(4, 128, NBR), 256, 81920>>>(Ahp, Alp, W2h, W2l, bufB, psum, psq,
                                                 512, MS512, 512L*512, 512);
    bn_finalize<<<16, 256>>>(psum, psq, mg2, mB2, sc + SL, sh + SL, NBR * 512);

    conv_bn<<<NBR * MROWS, 256>>>(bufB, sc + SL, sh + SL, Ahp, Alp);
    gemm_mma2<<<dim3(4, 128, NBR), 256, 81920>>>(Ahp, Alp, W3h, W3l, bufA, psum, psq,
                                                 512, MS512, 512L*512, 512);
    bn_finalize<<<16, 256>>>(psum, psq, mg3, mB3, sc + 2 * SL, sh + 2 * SL, NBR * 512);

    conv_bn<<<NBR * MROWS, 256>>>(bufA, sc + 2 * SL, sh + 2 * SL, Ahp, Alp);
    gemm_mma2<<<dim3(1, 128, NBR), 256, 81920>>>(Ahp, Alp, W4h, W4l, h4, psum, psq,
                                                 512, MS512, 128L*512, 64);
    bn_finalize<<<2, 256>>>(psum, psq, mg4, mB4, sc + 3 * SL, sh + 3 * SL, NBR * 64);

    gemm_bn<64, 4, true, true><<<dim3(1, 128, NBR), 256>>>(
        h4, aW1, t1, sc + 3 * SL, sh + 3 * SL, psum, psq, MROWS, 64, 64, MS64);
    bn_finalize<<<2, 256>>>(psum, psq, ag1, aB1, sc + 4 * SL, sh + 4 * SL, NBR * 64);

    gemm_bn<128, 8, true, true><<<dim3(1, 128, NBR), 256>>>(
        t1, aW2, t2, sc + 4 * SL, sh + 4 * SL, psum, psq, MROWS, 128, 64, MS64);
    bn_finalize<<<4, 256>>>(psum, psq, ag2, aB2, sc + 5 * SL, sh + 5 * SL, NBR * 128);

    gemm_bn<128, 8, true, false><<<dim3(1, 128, NBR), 256>>>(
        t2, aW3, t3, sc + 5 * SL, sh + 5 * SL, nullptr, nullptr, MROWS, 128, 128, MS128);

    softmax_pts_kernel<<<dim3(32, NBR), 256, 512 * 65 * 4>>>(
        t3, h4, sc + 3 * SL, sh + 3 * SL, aW4, ab4, out);

    cudaStreamWaitEvent(0, evJoin, 0);
}